// round 2
// baseline (speedup 1.0000x reference)
#include <cuda_runtime.h>
#include <math.h>

#define TQ 16
#define TK 32
#define S_LEN 2048
#define D_DIM 64
#define SSTRIDE 2052   // 2048 + 4 floats pad (stride/4 = 513, odd -> conflict floor)
#define KSTRIDE 68     // 64 + 4 floats pad  (stride/4 = 17,  odd -> conflict floor)

// SMEM layout (floats):
//   Stile [TQ][SSTRIDE]      : exp(scores) tile (unnormalized)
//   KV    [TK][KSTRIDE]      : staging for K chunk (phase 1) / V chunk (phase 3)
//   part  [TQ][16]           : per-thread rowsum partials
//   invs  [TQ]               : 1/rowsum
#define SMEM_FLOATS (TQ*SSTRIDE + TK*KSTRIDE + TQ*16 + TQ)

__global__ void __launch_bounds__(256, 1)
attn_fused_kernel(const float* __restrict__ Q,
                  const float* __restrict__ K,
                  const float* __restrict__ V,
                  const unsigned int* __restrict__ M,   // bool widened to 4 bytes by harness
                  float* __restrict__ p_val,
                  float* __restrict__ p_attn)
{
    extern __shared__ float smem[];
    float* Stile = smem;
    float* KV    = smem + TQ * SSTRIDE;
    float* part  = KV + TK * KSTRIDE;
    float* invs  = part + TQ * 16;

    const int tid = threadIdx.x;
    const int r   = tid >> 4;    // 0..15 : query row within tile
    const int c0  = tid & 15;    // 0..15 : column lane
    const int bh  = blockIdx.y;  // 0..31
    const int q0  = blockIdx.x * TQ;

    const float scale = 0.125f;  // 1/sqrt(64)

    // ---- load this thread's Q row into registers (broadcast across 16 lanes via L1) ----
    const float4* qrow = (const float4*)(Q + ((size_t)bh * S_LEN + q0 + r) * D_DIM);
    float4 qv[16];
#pragma unroll
    for (int i = 0; i < 16; i++) qv[i] = __ldg(qrow + i);

    const float* Kbh = K + (size_t)bh * S_LEN * D_DIM;
    const float* Vbh = V + (size_t)bh * S_LEN * D_DIM;
    // mask shape (1,1,S,S): row q0+r, independent of bh; 4-byte elements, nonzero == True
    const unsigned int* mrow = M + (size_t)(q0 + r) * S_LEN;

    float rowsum = 0.f;

    // ================= Phase 1: scores -> exp -> Stile =================
    for (int kb = 0; kb < S_LEN; kb += TK) {
        __syncthreads();
        // stage K chunk [TK][D] -> KV (coalesced float4)
        {
            const float4* src = (const float4*)(Kbh + (size_t)kb * D_DIM);
#pragma unroll
            for (int i = 0; i < 2; i++) {
                int idx  = tid + i * 256;      // 0..511 float4 index
                int row  = idx >> 4;           // /16 float4 per row
                int col4 = idx & 15;
                float4 v = __ldg(src + idx);
                *((float4*)(KV + row * KSTRIDE + col4 * 4)) = v;
            }
        }
        __syncthreads();

        // two independent dot products -> ILP to cover FFMA latency
        float a0 = 0.f, a1 = 0.f;
        const float* k0p = KV + c0 * KSTRIDE;
        const float* k1p = KV + (c0 + 16) * KSTRIDE;
#pragma unroll
        for (int i = 0; i < 16; i++) {
            float4 k0 = *((const float4*)(k0p + i * 4));
            float4 k1 = *((const float4*)(k1p + i * 4));
            a0 += qv[i].x * k0.x + qv[i].y * k0.y + qv[i].z * k0.z + qv[i].w * k0.w;
            a1 += qv[i].x * k1.x + qv[i].y * k1.y + qv[i].z * k1.z + qv[i].w * k1.w;
        }

        const int kg0 = kb + c0;
        const int kg1 = kb + c0 + 16;
        // mask nonzero -> masked -> exp(-1e9) == 0 exactly.
        // Works for int32 0/1 and float32 0.0/1.0 encodings alike.
        float e0 = (mrow[kg0] != 0u) ? 0.f : __expf(a0 * scale);
        float e1 = (mrow[kg1] != 0u) ? 0.f : __expf(a1 * scale);
        rowsum += e0 + e1;
        Stile[r * SSTRIDE + kg0] = e0;
        Stile[r * SSTRIDE + kg1] = e1;
    }

    // ================= Phase 2: row sums =================
    part[r * 16 + c0] = rowsum;
    __syncthreads();
    if (tid < TQ) {
        float s = 0.f;
#pragma unroll
        for (int i = 0; i < 16; i++) s += part[tid * 16 + i];
        invs[tid] = 1.0f / s;
    }
    __syncthreads();

    // ---- write normalized p_attn (coalesced float4, 128 KB per CTA) ----
    {
        float* out = p_attn + ((size_t)bh * S_LEN + q0) * S_LEN;
#pragma unroll
        for (int i = 0; i < 32; i++) {
            int idx  = tid + i * 256;   // float4 index in [0, 8192)
            int row  = idx >> 9;        // 512 float4 per row
            int col4 = idx & 511;
            float4 v = *((float4*)(Stile + row * SSTRIDE + col4 * 4));
            float inv = invs[row];
            v.x *= inv; v.y *= inv; v.z *= inv; v.w *= inv;
            *((float4*)(out + (size_t)row * S_LEN) + col4) = v;
        }
    }

    // ================= Phase 3: PV (p_val = P @ V) =================
    float4 acc = make_float4(0.f, 0.f, 0.f, 0.f);
    const float* prow = Stile + r * SSTRIDE;
    for (int kb = 0; kb < S_LEN; kb += TK) {
        __syncthreads();
        // stage V chunk [TK][D] -> KV
        {
            const float4* src = (const float4*)(Vbh + (size_t)kb * D_DIM);
#pragma unroll
            for (int i = 0; i < 2; i++) {
                int idx  = tid + i * 256;
                int row  = idx >> 4;
                int col4 = idx & 15;
                float4 v = __ldg(src + idx);
                *((float4*)(KV + row * KSTRIDE + col4 * 4)) = v;
            }
        }
        __syncthreads();
#pragma unroll
        for (int kk = 0; kk < TK; kk++) {
            float p  = prow[kb + kk];                                  // broadcast LDS
            float4 v = *((const float4*)(KV + kk * KSTRIDE + c0 * 4)); // 16-wide LDS.128
            acc.x += p * v.x; acc.y += p * v.y; acc.z += p * v.z; acc.w += p * v.w;
        }
    }
    const float inv = invs[r];
    acc.x *= inv; acc.y *= inv; acc.z *= inv; acc.w *= inv;
    float* outv = p_val + ((size_t)bh * S_LEN + q0 + r) * D_DIM;
    *((float4*)outv + c0) = acc;
}

extern "C" void kernel_launch(void* const* d_in, const int* in_sizes, int n_in,
                              void* d_out, int out_size)
{
    const float*        Q = (const float*)d_in[0];
    const float*        K = (const float*)d_in[1];
    const float*        V = (const float*)d_in[2];
    const unsigned int* M = (const unsigned int*)d_in[3];  // bool -> 4-byte (int32/float32)

    float* p_val  = (float*)d_out;                                   // B*H*S*D = 4,194,304
    float* p_attn = (float*)d_out + (size_t)2 * 16 * 2048 * 64;      // then B*H*S*S

    const size_t smem_bytes = (size_t)SMEM_FLOATS * sizeof(float);
    cudaFuncSetAttribute(attn_fused_kernel,
                         cudaFuncAttributeMaxDynamicSharedMemorySize,
                         (int)smem_bytes);

    dim3 grid(S_LEN / TQ, 32);   // (128 q-tiles, B*H)
    attn_fused_kernel<<<grid, 256, smem_bytes>>>(Q, K, V, M, p_val, p_attn);
}

// round 3
// speedup vs baseline: 2.2335x; 2.2335x over previous
#include <cuda_runtime.h>
#include <cuda_bf16.h>
#include <math.h>

#define S_LEN   2048
#define D_DIM   64
#define TQ      16
#define SSTRIDE 2052      // fp32 words per Stile row (odd/4 -> conflict-free f4)
#define P2STR   2050      // uint32 words per converted (Ph|Pl) row; < 2052 => in-place safe
#define KHSTR   34        // uint32 words per K row in stage (68 bf16)
#define VPSTR   66        // uint32 words per V d-row in stage (64 token-pairs + 2 pad)

// shared memory word offsets (fp32/uint32 words)
#define OFF_P    0                    // 16*2052 = 32832 words: Stile fp32, then in-place Ph/Pl
#define OFF_Q    32832                // 16*68 = 1088
#define OFF_KV   33920                // K stage: Kh 128*34=4352 | V stage: Vph 64*66=4224
#define OFF_KL   (33920 + 4352)      // Kl
#define OFF_VL   (33920 + 4224)      // Vpl
#define OFF_PART 42624                // 16*8
#define OFF_INV  42752                // 16
#define SMEM_WORDS 42768              // 171072 bytes

__device__ __forceinline__ void cvt_hilo2(float x, float y, unsigned &h, unsigned &l) {
    __nv_bfloat162 hh = __floats2bfloat162_rn(x, y);     // .x = x (low half), .y = y
    float rx = x - __bfloat162float(hh.x);
    float ry = y - __bfloat162float(hh.y);
    __nv_bfloat162 ll = __floats2bfloat162_rn(rx, ry);
    h = *reinterpret_cast<unsigned*>(&hh);
    l = *reinterpret_cast<unsigned*>(&ll);
}

#define MMA16816(C, A0, A1, A2, A3, B0, B1)                                        \
    asm volatile("mma.sync.aligned.m16n8k16.row.col.f32.bf16.bf16.f32 "            \
                 "{%0,%1,%2,%3},{%4,%5,%6,%7},{%8,%9},{%0,%1,%2,%3};\n"            \
                 : "+f"(C[0]), "+f"(C[1]), "+f"(C[2]), "+f"(C[3])                  \
                 : "r"(A0), "r"(A1), "r"(A2), "r"(A3), "r"(B0), "r"(B1))

__global__ void __launch_bounds__(256, 1)
attn_mma_kernel(const float* __restrict__ Q,
                const float* __restrict__ K,
                const float* __restrict__ V,
                const unsigned* __restrict__ M,   // bool widened to 4B; nonzero == masked
                float* __restrict__ p_val,
                float* __restrict__ p_attn)
{
    extern __shared__ float smem[];
    unsigned* smw = reinterpret_cast<unsigned*>(smem);

    const int tid  = threadIdx.x;
    const int warp = tid >> 5;
    const int lane = tid & 31;
    const int g    = lane >> 2;     // 0..7  (row group)
    const int tg   = lane & 3;      // 0..3  (thread-in-group)
    const int bh   = blockIdx.y;
    const int q0   = blockIdx.x * TQ;

    const float* Kbh = K + (size_t)bh * S_LEN * D_DIM;
    const float* Vbh = V + (size_t)bh * S_LEN * D_DIM;

    // ================= Q tile -> smem -> A fragments (hi/lo, 4 k-steps) ========
    {
        // 16 rows x 16 float4
        int row = tid >> 4, c4 = tid & 15;
        float4 qv = __ldg((const float4*)(Q + ((size_t)bh * S_LEN + q0 + row) * D_DIM) + c4);
        *((float4*)(smem + OFF_Q + row * 68 + c4 * 4)) = qv;
    }
    __syncthreads();

    unsigned ah[4][4], al[4][4];
#pragma unroll
    for (int ks = 0; ks < 4; ks++) {
        int c = ks * 16 + tg * 2;
        float2 x0 = *(const float2*)(smem + OFF_Q + g * 68 + c);
        float2 x1 = *(const float2*)(smem + OFF_Q + (g + 8) * 68 + c);
        float2 x2 = *(const float2*)(smem + OFF_Q + g * 68 + c + 8);
        float2 x3 = *(const float2*)(smem + OFF_Q + (g + 8) * 68 + c + 8);
        cvt_hilo2(x0.x, x0.y, ah[ks][0], al[ks][0]);
        cvt_hilo2(x1.x, x1.y, ah[ks][1], al[ks][1]);
        cvt_hilo2(x2.x, x2.y, ah[ks][2], al[ks][2]);
        cvt_hilo2(x3.x, x3.y, ah[ks][3], al[ks][3]);
    }

    // ================= Phase 1: QK^T (MMA) -> exp -> Stile =====================
    float rs0 = 0.f, rs1 = 0.f;   // rowsum partials for rows g, g+8
    const unsigned* KH = smw + OFF_KV;
    const unsigned* KL = smw + OFF_KL;

    for (int st = 0; st < 16; st++) {
        const int kb0 = st * 128;
        __syncthreads();
        {   // stage 128 K rows as bf16 hi/lo (pairs along d)
            const float4* src = (const float4*)(Kbh + (size_t)kb0 * D_DIM);
#pragma unroll
            for (int i = 0; i < 8; i++) {
                int idx = tid + i * 256;            // 0..2047
                int row = idx >> 4, c4 = idx & 15;
                float4 v = __ldg(src + idx);
                unsigned h0, l0, h1, l1;
                cvt_hilo2(v.x, v.y, h0, l0);
                cvt_hilo2(v.z, v.w, h1, l1);
                int w = row * KHSTR + c4 * 2;
                smw[OFF_KV + w] = h0; smw[OFF_KV + w + 1] = h1;
                smw[OFF_KL + w] = l0; smw[OFF_KL + w + 1] = l1;
            }
        }
        __syncthreads();

        // this warp's two n-tiles within the stage
        const int ln0 = warp * 16;      // local col base of tile 0
        float C0[4] = {0.f, 0.f, 0.f, 0.f};
        float C1[4] = {0.f, 0.f, 0.f, 0.f};
#pragma unroll
        for (int ks = 0; ks < 4; ks++) {
            int w0 = (ln0 + g) * KHSTR + ks * 8 + tg;
            int w1 = (ln0 + 8 + g) * KHSTR + ks * 8 + tg;
            unsigned b0h0 = KH[w0], b0h1 = KH[w0 + 4];
            unsigned b1h0 = KH[w1], b1h1 = KH[w1 + 4];
            unsigned b0l0 = KL[w0], b0l1 = KL[w0 + 4];
            unsigned b1l0 = KL[w1], b1l1 = KL[w1 + 4];
            MMA16816(C0, ah[ks][0], ah[ks][1], ah[ks][2], ah[ks][3], b0h0, b0h1);
            MMA16816(C1, ah[ks][0], ah[ks][1], ah[ks][2], ah[ks][3], b1h0, b1h1);
            MMA16816(C0, al[ks][0], al[ks][1], al[ks][2], al[ks][3], b0h0, b0h1);
            MMA16816(C1, al[ks][0], al[ks][1], al[ks][2], al[ks][3], b1h0, b1h1);
            MMA16816(C0, ah[ks][0], ah[ks][1], ah[ks][2], ah[ks][3], b0l0, b0l1);
            MMA16816(C1, ah[ks][0], ah[ks][1], ah[ks][2], ah[ks][3], b1l0, b1l1);
        }

        // epilogue: scale, mask, exp, rowsum, store to Stile
#pragma unroll
        for (int t = 0; t < 2; t++) {
            const float* C = t ? C1 : C0;
            int nb = kb0 + ln0 + t * 8 + tg * 2;
            uint2 m0 = *(const uint2*)(M + (size_t)(q0 + g) * S_LEN + nb);
            uint2 m1 = *(const uint2*)(M + (size_t)(q0 + g + 8) * S_LEN + nb);
            float e00 = m0.x ? 0.f : __expf(C[0] * 0.125f);
            float e01 = m0.y ? 0.f : __expf(C[1] * 0.125f);
            float e10 = m1.x ? 0.f : __expf(C[2] * 0.125f);
            float e11 = m1.y ? 0.f : __expf(C[3] * 0.125f);
            rs0 += e00 + e01;
            rs1 += e10 + e11;
            *(float2*)(smem + g * SSTRIDE + nb)       = make_float2(e00, e01);
            *(float2*)(smem + (g + 8) * SSTRIDE + nb) = make_float2(e10, e11);
        }
    }

    // ================= rowsums -> invs ========================================
    rs0 += __shfl_xor_sync(0xffffffff, rs0, 1);
    rs0 += __shfl_xor_sync(0xffffffff, rs0, 2);
    rs1 += __shfl_xor_sync(0xffffffff, rs1, 1);
    rs1 += __shfl_xor_sync(0xffffffff, rs1, 2);
    if (tg == 0) {
        smem[OFF_PART + g * 8 + warp]       = rs0;
        smem[OFF_PART + (g + 8) * 8 + warp] = rs1;
    }
    __syncthreads();
    if (tid < TQ) {
        float s = 0.f;
#pragma unroll
        for (int i = 0; i < 8; i++) s += smem[OFF_PART + tid * 8 + i];
        smem[OFF_INV + tid] = 1.0f / s;
    }
    __syncthreads();

    // ================= Phase 2: write normalized p_attn =======================
    {
        float* out = p_attn + ((size_t)bh * S_LEN + q0) * S_LEN;
        const float4* Sf4 = (const float4*)smem;
#pragma unroll
        for (int i = 0; i < 32; i++) {
            int idx  = tid + i * 256;
            int row  = idx >> 9;
            int col4 = idx & 511;
            float4 v = Sf4[row * 513 + col4];
            float inv = smem[OFF_INV + row];
            v.x *= inv; v.y *= inv; v.z *= inv; v.w *= inv;
            *((float4*)(out + (size_t)row * S_LEN) + col4) = v;
        }
    }
    __syncthreads();

    // ================= Phase 2.5: in-place Stile fp32 -> Ph|Pl bf16 ===========
    // row r: Ph at words P2STR*r + [0,1024), Pl at +1024. Writes stay below the
    // fp32 cells of rows > r; same-row hazard handled by read -> sync -> write.
    for (int r = 0; r < TQ; r++) {
        const float4* Sf4 = (const float4*)smem;
        float4 v0 = Sf4[r * 513 + tid];          // cols 4*tid   .. +3
        float4 v1 = Sf4[r * 513 + 256 + tid];    // cols 1024+4*tid ..
        __syncthreads();
        unsigned h, l;
        unsigned* base = smw + (size_t)P2STR * r;
        cvt_hilo2(v0.x, v0.y, h, l); base[2 * tid] = h;     base[1024 + 2 * tid] = l;
        cvt_hilo2(v0.z, v0.w, h, l); base[2 * tid + 1] = h; base[1024 + 2 * tid + 1] = l;
        cvt_hilo2(v1.x, v1.y, h, l); base[512 + 2 * tid] = h;     base[1536 + 2 * tid] = l;
        cvt_hilo2(v1.z, v1.w, h, l); base[512 + 2 * tid + 1] = h; base[1536 + 2 * tid + 1] = l;
        __syncthreads();
    }

    // ================= Phase 3: PV (MMA), warp w owns d-cols 8w..8w+7 =========
    float Oa[4] = {0.f, 0.f, 0.f, 0.f};
    float Ob[4] = {0.f, 0.f, 0.f, 0.f};
    const unsigned* VPH = smw + OFF_KV;
    const unsigned* VPL = smw + OFF_VL;
    const unsigned* PHg  = smw + (size_t)P2STR * g;
    const unsigned* PHg8 = smw + (size_t)P2STR * (g + 8);

    for (int st = 0; st < 16; st++) {
        __syncthreads();
        {   // stage 128 V tokens, packed as token-pairs per d-row (bf16 hi/lo)
            const float4* src = (const float4*)(Vbh + (size_t)st * 128 * D_DIM);
#pragma unroll
            for (int i = 0; i < 4; i++) {
                int pidx = tid + i * 256;            // 0..1023
                int tp = pidx >> 4, c4 = pidx & 15;  // token pair, d-float4
                float4 u0 = __ldg(src + (2 * tp) * 16 + c4);
                float4 u1 = __ldg(src + (2 * tp + 1) * 16 + c4);
                unsigned h, l;
                int d0 = c4 * 4;
                cvt_hilo2(u0.x, u1.x, h, l); smw[OFF_KV + (d0    ) * VPSTR + tp] = h; smw[OFF_VL + (d0    ) * VPSTR + tp] = l;
                cvt_hilo2(u0.y, u1.y, h, l); smw[OFF_KV + (d0 + 1) * VPSTR + tp] = h; smw[OFF_VL + (d0 + 1) * VPSTR + tp] = l;
                cvt_hilo2(u0.z, u1.z, h, l); smw[OFF_KV + (d0 + 2) * VPSTR + tp] = h; smw[OFF_VL + (d0 + 2) * VPSTR + tp] = l;
                cvt_hilo2(u0.w, u1.w, h, l); smw[OFF_KV + (d0 + 3) * VPSTR + tp] = h; smw[OFF_VL + (d0 + 3) * VPSTR + tp] = l;
            }
        }
        __syncthreads();

#pragma unroll
        for (int kl = 0; kl < 8; kl += 2) {
            // --- k-chunk kc = st*8 + kl  -> Oa ---
            {
                int kc = st * 8 + kl;
                int wa = kc * 8 + tg;
                unsigned A0 = PHg[wa],        A1 = PHg8[wa];
                unsigned A2 = PHg[wa + 4],    A3 = PHg8[wa + 4];
                unsigned L0 = PHg[wa + 1024], L1 = PHg8[wa + 1024];
                unsigned L2 = PHg[wa + 1028], L3 = PHg8[wa + 1028];
                int wb = (warp * 8 + g) * VPSTR + kl * 8 + tg;
                unsigned bh0 = VPH[wb], bh1 = VPH[wb + 4];
                unsigned bl0 = VPL[wb], bl1 = VPL[wb + 4];
                MMA16816(Oa, A0, A1, A2, A3, bh0, bh1);
                MMA16816(Oa, L0, L1, L2, L3, bh0, bh1);
                MMA16816(Oa, A0, A1, A2, A3, bl0, bl1);
            }
            // --- k-chunk kc+1 -> Ob (independent chain) ---
            {
                int kc = st * 8 + kl + 1;
                int wa = kc * 8 + tg;
                unsigned A0 = PHg[wa],        A1 = PHg8[wa];
                unsigned A2 = PHg[wa + 4],    A3 = PHg8[wa + 4];
                unsigned L0 = PHg[wa + 1024], L1 = PHg8[wa + 1024];
                unsigned L2 = PHg[wa + 1028], L3 = PHg8[wa + 1028];
                int wb = (warp * 8 + g) * VPSTR + (kl + 1) * 8 + tg;
                unsigned bh0 = VPH[wb], bh1 = VPH[wb + 4];
                unsigned bl0 = VPL[wb], bl1 = VPL[wb + 4];
                MMA16816(Ob, A0, A1, A2, A3, bh0, bh1);
                MMA16816(Ob, L0, L1, L2, L3, bh0, bh1);
                MMA16816(Ob, A0, A1, A2, A3, bl0, bl1);
            }
        }
    }

    // write p_val (normalize by rowsum)
    {
        float inv0 = smem[OFF_INV + g];
        float inv1 = smem[OFF_INV + g + 8];
        int d0 = warp * 8 + tg * 2;
        float* o0 = p_val + ((size_t)bh * S_LEN + q0 + g) * D_DIM + d0;
        float* o1 = p_val + ((size_t)bh * S_LEN + q0 + g + 8) * D_DIM + d0;
        *(float2*)o0 = make_float2((Oa[0] + Ob[0]) * inv0, (Oa[1] + Ob[1]) * inv0);
        *(float2*)o1 = make_float2((Oa[2] + Ob[2]) * inv1, (Oa[3] + Ob[3]) * inv1);
    }
}

extern "C" void kernel_launch(void* const* d_in, const int* in_sizes, int n_in,
                              void* d_out, int out_size)
{
    const float*    Q = (const float*)d_in[0];
    const float*    K = (const float*)d_in[1];
    const float*    V = (const float*)d_in[2];
    const unsigned* M = (const unsigned*)d_in[3];

    float* p_val  = (float*)d_out;
    float* p_attn = (float*)d_out + (size_t)2 * 16 * 2048 * 64;

    const size_t smem_bytes = (size_t)SMEM_WORDS * sizeof(float);  // 171072
    cudaFuncSetAttribute(attn_mma_kernel,
                         cudaFuncAttributeMaxDynamicSharedMemorySize,
                         (int)smem_bytes);

    dim3 grid(S_LEN / TQ, 32);
    attn_mma_kernel<<<grid, 256, smem_bytes>>>(Q, K, V, M, p_val, p_attn);
}

// round 4
// speedup vs baseline: 2.7418x; 1.2276x over previous
#include <cuda_runtime.h>
#include <cuda_bf16.h>
#include <math.h>

#define S_LEN   2048
#define D_DIM   64
#define TQ      16
#define SSTRIDE 2052      // fp32 words per Stile row (513 float4 -> conflict-free)
#define KHSTR   34        // uint32 words per K token row (32 data + 2 pad)
#define VPSTR   66        // uint32 words per V d-row (64 token-pairs + 2 pad)
#define REDSTR  68        // fp32 words per row in O-reduction area (16B aligned)

// shared memory word offsets
#define OFF_STILE 0                    // 16*2052 = 32832
#define OFF_Q     32832                // 16*68   = 1088
#define OFF_KH    33920                // 128*34  = 4352
#define OFF_KL    38272                // 128*34  = 4352
#define OFF_VH    42624                // 64*66   = 4224
#define OFF_VL    46848                // 64*66   = 4224
#define OFF_PART  51072                // 16*8
#define OFF_INV   51200                // 16
#define SMEM_WORDS 51216               // 204864 bytes
// O-reduction overlays KH/KL after the main loop: 8 warps * 16*68 = 8704 words
#define OFF_RED   OFF_KH

__device__ __forceinline__ void cvt_hilo2(float x, float y, unsigned &h, unsigned &l) {
    __nv_bfloat162 hh = __floats2bfloat162_rn(x, y);     // .x = x (low half)
    float rx = x - __bfloat162float(hh.x);
    float ry = y - __bfloat162float(hh.y);
    __nv_bfloat162 ll = __floats2bfloat162_rn(rx, ry);
    h = *reinterpret_cast<unsigned*>(&hh);
    l = *reinterpret_cast<unsigned*>(&ll);
}

#define MMA16816(C, A0, A1, A2, A3, B0, B1)                                        \
    asm volatile("mma.sync.aligned.m16n8k16.row.col.f32.bf16.bf16.f32 "            \
                 "{%0,%1,%2,%3},{%4,%5,%6,%7},{%8,%9},{%0,%1,%2,%3};\n"            \
                 : "+f"(C[0]), "+f"(C[1]), "+f"(C[2]), "+f"(C[3])                  \
                 : "r"(A0), "r"(A1), "r"(A2), "r"(A3), "r"(B0), "r"(B1))

__global__ void __launch_bounds__(256, 1)
attn_flash_kernel(const float* __restrict__ Q,
                  const float* __restrict__ K,
                  const float* __restrict__ V,
                  const unsigned* __restrict__ M,   // bool widened to 4B; nonzero == masked
                  float* __restrict__ p_val,
                  float* __restrict__ p_attn)
{
    extern __shared__ float smem[];
    unsigned* smw = reinterpret_cast<unsigned*>(smem);

    const int tid  = threadIdx.x;
    const int warp = tid >> 5;
    const int lane = tid & 31;
    const int g    = lane >> 2;     // 0..7  (row group)
    const int tg   = lane & 3;      // 0..3  (thread-in-group)
    const int bh   = blockIdx.y;
    const int q0   = blockIdx.x * TQ;

    const float* Kbh = K + (size_t)bh * S_LEN * D_DIM;
    const float* Vbh = V + (size_t)bh * S_LEN * D_DIM;

    // ================= Q tile -> smem -> A fragments (hi/lo, 4 k-steps) ========
    {
        int row = tid >> 4, c4 = tid & 15;
        float4 qv = __ldg((const float4*)(Q + ((size_t)bh * S_LEN + q0 + row) * D_DIM) + c4);
        *((float4*)(smem + OFF_Q + row * 68 + c4 * 4)) = qv;
    }
    __syncthreads();

    unsigned qah[4][4], qal[4][4];
#pragma unroll
    for (int ks = 0; ks < 4; ks++) {
        int c = ks * 16 + tg * 2;
        float2 x0 = *(const float2*)(smem + OFF_Q + g * 68 + c);
        float2 x1 = *(const float2*)(smem + OFF_Q + (g + 8) * 68 + c);
        float2 x2 = *(const float2*)(smem + OFF_Q + g * 68 + c + 8);
        float2 x3 = *(const float2*)(smem + OFF_Q + (g + 8) * 68 + c + 8);
        cvt_hilo2(x0.x, x0.y, qah[ks][0], qal[ks][0]);
        cvt_hilo2(x1.x, x1.y, qah[ks][1], qal[ks][1]);
        cvt_hilo2(x2.x, x2.y, qah[ks][2], qal[ks][2]);
        cvt_hilo2(x3.x, x3.y, qah[ks][3], qal[ks][3]);
    }

    const unsigned* KH = smw + OFF_KH;
    const unsigned* KL = smw + OFF_KL;
    const unsigned* VH = smw + OFF_VH;
    const unsigned* VL = smw + OFF_VL;
    const int ln0 = warp * 16;          // this warp's token slice within a stage

    float rs0 = 0.f, rs1 = 0.f;         // rowsum partials (rows g, g+8; this warp's tokens)
    float O[8][4];                      // partial PV accumulators: n-tile j -> d = 8j..8j+7
#pragma unroll
    for (int j = 0; j < 8; j++) { O[j][0] = O[j][1] = O[j][2] = O[j][3] = 0.f; }

    // =================== fused main loop over 16 stages of 128 tokens ==========
    for (int st = 0; st < 16; st++) {
        const int kb0 = st * 128;
        __syncthreads();
        // ---- stage K: 128 tokens x 64 d as bf16 hi/lo (d-pairs packed) ----
        {
            const float4* src = (const float4*)(Kbh + (size_t)kb0 * D_DIM);
#pragma unroll
            for (int i = 0; i < 8; i++) {
                int idx = tid + i * 256;            // 0..2047
                int row = idx >> 4, c4 = idx & 15;
                float4 v = __ldg(src + idx);
                unsigned h0, l0, h1, l1;
                cvt_hilo2(v.x, v.y, h0, l0);
                cvt_hilo2(v.z, v.w, h1, l1);
                int w = row * KHSTR + c4 * 2;
                smw[OFF_KH + w] = h0; smw[OFF_KH + w + 1] = h1;
                smw[OFF_KL + w] = l0; smw[OFF_KL + w + 1] = l1;
            }
        }
        // ---- stage V: 128 tokens packed as token-pairs per d-row (hi/lo) ----
        {
            const float4* src = (const float4*)(Vbh + (size_t)kb0 * D_DIM);
#pragma unroll
            for (int i = 0; i < 4; i++) {
                int pidx = tid + i * 256;            // 0..1023
                int tp = pidx >> 4, c4 = pidx & 15;  // token pair, d-float4
                float4 u0 = __ldg(src + (2 * tp) * 16 + c4);
                float4 u1 = __ldg(src + (2 * tp + 1) * 16 + c4);
                unsigned h, l;
                int d0 = c4 * 4;
                cvt_hilo2(u0.x, u1.x, h, l); smw[OFF_VH + (d0    ) * VPSTR + tp] = h; smw[OFF_VL + (d0    ) * VPSTR + tp] = l;
                cvt_hilo2(u0.y, u1.y, h, l); smw[OFF_VH + (d0 + 1) * VPSTR + tp] = h; smw[OFF_VL + (d0 + 1) * VPSTR + tp] = l;
                cvt_hilo2(u0.z, u1.z, h, l); smw[OFF_VH + (d0 + 2) * VPSTR + tp] = h; smw[OFF_VL + (d0 + 2) * VPSTR + tp] = l;
                cvt_hilo2(u0.w, u1.w, h, l); smw[OFF_VH + (d0 + 3) * VPSTR + tp] = h; smw[OFF_VL + (d0 + 3) * VPSTR + tp] = l;
            }
        }
        __syncthreads();

        // ---- QK^T for this warp's 16 tokens (two n-tiles), 3-term hi/lo ----
        float C0[4] = {0.f, 0.f, 0.f, 0.f};
        float C1[4] = {0.f, 0.f, 0.f, 0.f};
#pragma unroll
        for (int ks = 0; ks < 4; ks++) {
            int w0 = (ln0 + g) * KHSTR + ks * 8 + tg;
            int w1 = (ln0 + 8 + g) * KHSTR + ks * 8 + tg;
            unsigned b0h0 = KH[w0], b0h1 = KH[w0 + 4];
            unsigned b1h0 = KH[w1], b1h1 = KH[w1 + 4];
            unsigned b0l0 = KL[w0], b0l1 = KL[w0 + 4];
            unsigned b1l0 = KL[w1], b1l1 = KL[w1 + 4];
            MMA16816(C0, qah[ks][0], qah[ks][1], qah[ks][2], qah[ks][3], b0h0, b0h1);
            MMA16816(C1, qah[ks][0], qah[ks][1], qah[ks][2], qah[ks][3], b1h0, b1h1);
            MMA16816(C0, qal[ks][0], qal[ks][1], qal[ks][2], qal[ks][3], b0h0, b0h1);
            MMA16816(C1, qal[ks][0], qal[ks][1], qal[ks][2], qal[ks][3], b1h0, b1h1);
            MMA16816(C0, qah[ks][0], qah[ks][1], qah[ks][2], qah[ks][3], b0l0, b0l1);
            MMA16816(C1, qah[ks][0], qah[ks][1], qah[ks][2], qah[ks][3], b1l0, b1l1);
        }

        // ---- epilogue: mask, exp, rowsum, Stile store; E stays in registers ----
        float e[2][4];
#pragma unroll
        for (int t = 0; t < 2; t++) {
            const float* C = t ? C1 : C0;
            int nb = kb0 + ln0 + t * 8 + tg * 2;
            uint2 m0 = *(const uint2*)(M + (size_t)(q0 + g) * S_LEN + nb);
            uint2 m1 = *(const uint2*)(M + (size_t)(q0 + g + 8) * S_LEN + nb);
            e[t][0] = m0.x ? 0.f : __expf(C[0] * 0.125f);
            e[t][1] = m0.y ? 0.f : __expf(C[1] * 0.125f);
            e[t][2] = m1.x ? 0.f : __expf(C[2] * 0.125f);
            e[t][3] = m1.y ? 0.f : __expf(C[3] * 0.125f);
            rs0 += e[t][0] + e[t][1];
            rs1 += e[t][2] + e[t][3];
            *(float2*)(smem + g * SSTRIDE + nb)       = make_float2(e[t][0], e[t][1]);
            *(float2*)(smem + (g + 8) * SSTRIDE + nb) = make_float2(e[t][2], e[t][3]);
        }

        // ---- convert E (C-frag) -> A-frag hi/lo in registers (layout identical) ----
        unsigned Ah[4], Al[4];
        cvt_hilo2(e[0][0], e[0][1], Ah[0], Al[0]);   // row g,   k 2tg,2tg+1
        cvt_hilo2(e[0][2], e[0][3], Ah[1], Al[1]);   // row g+8, k 2tg,2tg+1
        cvt_hilo2(e[1][0], e[1][1], Ah[2], Al[2]);   // row g,   k 8+2tg
        cvt_hilo2(e[1][2], e[1][3], Ah[3], Al[3]);   // row g+8, k 8+2tg

        // ---- PV: this warp's 16 tokens against V, all 64 d (8 n-tiles) ----
#pragma unroll
        for (int j = 0; j < 8; j++) {
            int wb = (j * 8 + g) * VPSTR + warp * 8 + tg;
            unsigned bh0 = VH[wb], bh1 = VH[wb + 4];
            unsigned bl0 = VL[wb], bl1 = VL[wb + 4];
            MMA16816(O[j], Ah[0], Ah[1], Ah[2], Ah[3], bh0, bh1);
            MMA16816(O[j], Al[0], Al[1], Al[2], Al[3], bh0, bh1);
            MMA16816(O[j], Ah[0], Ah[1], Ah[2], Ah[3], bl0, bl1);
        }
    }

    // ================= rowsums -> invs ========================================
    rs0 += __shfl_xor_sync(0xffffffff, rs0, 1);
    rs0 += __shfl_xor_sync(0xffffffff, rs0, 2);
    rs1 += __shfl_xor_sync(0xffffffff, rs1, 1);
    rs1 += __shfl_xor_sync(0xffffffff, rs1, 2);
    if (tg == 0) {
        smem[OFF_PART + g * 8 + warp]       = rs0;
        smem[OFF_PART + (g + 8) * 8 + warp] = rs1;
    }

    // ---- write per-warp O partials into reduction area (overlays K stage) ----
    {
        float* base = smem + OFF_RED + warp * (16 * REDSTR);
#pragma unroll
        for (int j = 0; j < 8; j++) {
            *(float2*)(base + g * REDSTR + j * 8 + 2 * tg)       = make_float2(O[j][0], O[j][1]);
            *(float2*)(base + (g + 8) * REDSTR + j * 8 + 2 * tg) = make_float2(O[j][2], O[j][3]);
        }
    }
    __syncthreads();

    if (tid < TQ) {
        float s = 0.f;
#pragma unroll
        for (int i = 0; i < 8; i++) s += smem[OFF_PART + tid * 8 + i];
        smem[OFF_INV + tid] = 1.0f / s;
    }
    __syncthreads();

    // ================= reduce O partials across warps, write p_val ============
    {
        int row = tid >> 4;
        int d0  = (tid & 15) * 4;
        float4 acc = make_float4(0.f, 0.f, 0.f, 0.f);
#pragma unroll
        for (int w = 0; w < 8; w++) {
            float4 v = *(const float4*)(smem + OFF_RED + w * (16 * REDSTR) + row * REDSTR + d0);
            acc.x += v.x; acc.y += v.y; acc.z += v.z; acc.w += v.w;
        }
        float inv = smem[OFF_INV + row];
        acc.x *= inv; acc.y *= inv; acc.z *= inv; acc.w *= inv;
        *(float4*)(p_val + ((size_t)bh * S_LEN + q0 + row) * D_DIM + d0) = acc;
    }

    // ================= write normalized p_attn ================================
    {
        float* out = p_attn + ((size_t)bh * S_LEN + q0) * S_LEN;
        const float4* Sf4 = (const float4*)smem;
#pragma unroll
        for (int i = 0; i < 32; i++) {
            int idx  = tid + i * 256;
            int row  = idx >> 9;
            int col4 = idx & 511;
            float4 v = Sf4[row * 513 + col4];
            float inv = smem[OFF_INV + row];
            v.x *= inv; v.y *= inv; v.z *= inv; v.w *= inv;
            *((float4*)(out + (size_t)row * S_LEN) + col4) = v;
        }
    }
}

extern "C" void kernel_launch(void* const* d_in, const int* in_sizes, int n_in,
                              void* d_out, int out_size)
{
    const float*    Q = (const float*)d_in[0];
    const float*    K = (const float*)d_in[1];
    const float*    V = (const float*)d_in[2];
    const unsigned* M = (const unsigned*)d_in[3];

    float* p_val  = (float*)d_out;
    float* p_attn = (float*)d_out + (size_t)2 * 16 * 2048 * 64;

    const size_t smem_bytes = (size_t)SMEM_WORDS * sizeof(float);  // 204864
    cudaFuncSetAttribute(attn_flash_kernel,
                         cudaFuncAttributeMaxDynamicSharedMemorySize,
                         (int)smem_bytes);

    dim3 grid(S_LEN / TQ, 32);
    attn_flash_kernel<<<grid, 256, smem_bytes>>>(Q, K, V, M, p_val, p_attn);
}

// round 5
// speedup vs baseline: 3.5146x; 1.2819x over previous
#include <cuda_runtime.h>
#include <cuda_bf16.h>
#include <math.h>

#define S_LEN   2048
#define D_DIM   64
#define TQ      16
#define SSTRIDE 2056      // fp32 words per Stile row (mod 32 = 8 -> conflict-free f2 stores)
#define KVSTR   36        // uint32 words per token row (32 data + 4 pad; mod 32 = 4 -> LDSM-clean)
#define REDSTR  68        // fp32 words per row in O-reduction area

// shared memory word offsets
#define OFF_STILE 0                    // 16*2056 = 32896
#define OFF_Q     32896                // 16*68   = 1088
#define OFF_KH    33984                // 128*36  = 4608
#define OFF_KL    38592                // 4608
#define OFF_VH    43200                // 4608
#define OFF_VL    47808                // 4608
#define OFF_PART  52416                // 16*8
#define OFF_INV   52544                // 16
#define SMEM_WORDS 52560               // 210240 bytes
#define OFF_RED   OFF_KH               // O-reduction overlays KH/KL: 8*16*68 = 8704 words

__device__ __forceinline__ void cvt_hilo2(float x, float y, unsigned &h, unsigned &l) {
    __nv_bfloat162 hh = __floats2bfloat162_rn(x, y);     // .x = x (low half)
    float rx = x - __bfloat162float(hh.x);
    float ry = y - __bfloat162float(hh.y);
    __nv_bfloat162 ll = __floats2bfloat162_rn(rx, ry);
    h = *reinterpret_cast<unsigned*>(&hh);
    l = *reinterpret_cast<unsigned*>(&ll);
}

#define MMA16816(C, A0, A1, A2, A3, B0, B1)                                        \
    asm volatile("mma.sync.aligned.m16n8k16.row.col.f32.bf16.bf16.f32 "            \
                 "{%0,%1,%2,%3},{%4,%5,%6,%7},{%8,%9},{%0,%1,%2,%3};\n"            \
                 : "+f"(C[0]), "+f"(C[1]), "+f"(C[2]), "+f"(C[3])                  \
                 : "r"(A0), "r"(A1), "r"(A2), "r"(A3), "r"(B0), "r"(B1))

#define LDSM_X4(R0, R1, R2, R3, ADDR)                                              \
    asm volatile("ldmatrix.sync.aligned.m8n8.x4.shared.b16 {%0,%1,%2,%3}, [%4];"  \
                 : "=r"(R0), "=r"(R1), "=r"(R2), "=r"(R3) : "r"(ADDR))

#define LDSM_X4_T(R0, R1, R2, R3, ADDR)                                            \
    asm volatile("ldmatrix.sync.aligned.m8n8.x4.trans.shared.b16 {%0,%1,%2,%3}, [%4];" \
                 : "=r"(R0), "=r"(R1), "=r"(R2), "=r"(R3) : "r"(ADDR))

__global__ void __launch_bounds__(256, 1)
attn_flash_kernel(const float* __restrict__ Q,
                  const float* __restrict__ K,
                  const float* __restrict__ V,
                  const unsigned* __restrict__ M,   // bool widened to 4B; nonzero == masked
                  float* __restrict__ p_val,
                  float* __restrict__ p_attn)
{
    extern __shared__ float smem[];
    unsigned* smw = reinterpret_cast<unsigned*>(smem);
    const unsigned smem_u32 = (unsigned)__cvta_generic_to_shared(smem);

    const int tid  = threadIdx.x;
    const int warp = tid >> 5;
    const int lane = tid & 31;
    const int g    = lane >> 2;     // 0..7
    const int tg   = lane & 3;      // 0..3
    const int bh   = blockIdx.y;
    const int q0   = blockIdx.x * TQ;
    const int ln0  = warp * 16;     // this warp's token slice within a stage

    const float* Kbh = K + (size_t)bh * S_LEN * D_DIM;
    const float* Vbh = V + (size_t)bh * S_LEN * D_DIM;

    // ---- ldmatrix per-lane byte addresses (constant across stages) ----
    // QK (non-trans): mats {0,1}: tokens ln0+i, k-halves 0/+4w; {2,3}: tokens ln0+8+i
    const int qk_row  = ln0 + ((lane >> 4) << 3) + (lane & 7);
    const unsigned qk_off = (unsigned)(qk_row * KVSTR + (((lane >> 3) & 1) << 2)) * 4u;
    const unsigned kh_base = smem_u32 + OFF_KH * 4u + qk_off;
    const unsigned kl_base = smem_u32 + OFF_KL * 4u + qk_off;
    // PV (trans): mats {0,1}: tokens ln0+i / ln0+8+i at d-half 0; {2,3}: same rows at +4w
    const int pv_row  = ln0 + (((lane >> 3) & 1) << 3) + (lane & 7);
    const unsigned pv_off = (unsigned)(pv_row * KVSTR + ((lane >> 4) << 2)) * 4u;
    const unsigned vh_base = smem_u32 + OFF_VH * 4u + pv_off;
    const unsigned vl_base = smem_u32 + OFF_VL * 4u + pv_off;

    // ================= Q tile -> smem -> A fragments (hi/lo, 4 k-steps) ========
    {
        int row = tid >> 4, c4 = tid & 15;
        float4 qv = __ldg((const float4*)(Q + ((size_t)bh * S_LEN + q0 + row) * D_DIM) + c4);
        *((float4*)(smem + OFF_Q + row * 68 + c4 * 4)) = qv;
    }
    __syncthreads();

    unsigned qah[4][4], qal[4][4];
#pragma unroll
    for (int ks = 0; ks < 4; ks++) {
        int c = ks * 16 + tg * 2;
        float2 x0 = *(const float2*)(smem + OFF_Q + g * 68 + c);
        float2 x1 = *(const float2*)(smem + OFF_Q + (g + 8) * 68 + c);
        float2 x2 = *(const float2*)(smem + OFF_Q + g * 68 + c + 8);
        float2 x3 = *(const float2*)(smem + OFF_Q + (g + 8) * 68 + c + 8);
        cvt_hilo2(x0.x, x0.y, qah[ks][0], qal[ks][0]);
        cvt_hilo2(x1.x, x1.y, qah[ks][1], qal[ks][1]);
        cvt_hilo2(x2.x, x2.y, qah[ks][2], qal[ks][2]);
        cvt_hilo2(x3.x, x3.y, qah[ks][3], qal[ks][3]);
    }

    float rs0 = 0.f, rs1 = 0.f;
    float O[8][4];
#pragma unroll
    for (int j = 0; j < 8; j++) { O[j][0] = O[j][1] = O[j][2] = O[j][3] = 0.f; }

    // =================== fused main loop over 16 stages of 128 tokens ==========
    for (int st = 0; st < 16; st++) {
        const int kb0 = st * 128;
        __syncthreads();
        // ---- stage K and V: 128 token rows x 64 d, bf16 hi/lo, row stride 36 ----
        {
            const float4* srcK = (const float4*)(Kbh + (size_t)kb0 * D_DIM);
            const float4* srcV = (const float4*)(Vbh + (size_t)kb0 * D_DIM);
#pragma unroll
            for (int i = 0; i < 8; i++) {
                int idx = tid + i * 256;            // 0..2047
                int row = idx >> 4, c4 = idx & 15;
                int w = row * KVSTR + c4 * 2;
                float4 kv = __ldg(srcK + idx);
                unsigned h0, l0, h1, l1;
                cvt_hilo2(kv.x, kv.y, h0, l0);
                cvt_hilo2(kv.z, kv.w, h1, l1);
                *(uint2*)(smw + OFF_KH + w) = make_uint2(h0, h1);   // STS.64 conflict-free
                *(uint2*)(smw + OFF_KL + w) = make_uint2(l0, l1);
                float4 vv = __ldg(srcV + idx);
                cvt_hilo2(vv.x, vv.y, h0, l0);
                cvt_hilo2(vv.z, vv.w, h1, l1);
                *(uint2*)(smw + OFF_VH + w) = make_uint2(h0, h1);
                *(uint2*)(smw + OFF_VL + w) = make_uint2(l0, l1);
            }
        }
        __syncthreads();

        // ---- QK^T for this warp's 16 tokens (two n-tiles), 3-term hi/lo ----
        float C0[4] = {0.f, 0.f, 0.f, 0.f};
        float C1[4] = {0.f, 0.f, 0.f, 0.f};
#pragma unroll
        for (int ks = 0; ks < 4; ks++) {
            unsigned bh0, bh1, bh2, bh3, bl0, bl1, bl2, bl3;
            LDSM_X4(bh0, bh1, bh2, bh3, kh_base + ks * 32u);
            LDSM_X4(bl0, bl1, bl2, bl3, kl_base + ks * 32u);
            MMA16816(C0, qah[ks][0], qah[ks][1], qah[ks][2], qah[ks][3], bh0, bh1);
            MMA16816(C1, qah[ks][0], qah[ks][1], qah[ks][2], qah[ks][3], bh2, bh3);
            MMA16816(C0, qal[ks][0], qal[ks][1], qal[ks][2], qal[ks][3], bh0, bh1);
            MMA16816(C1, qal[ks][0], qal[ks][1], qal[ks][2], qal[ks][3], bh2, bh3);
            MMA16816(C0, qah[ks][0], qah[ks][1], qah[ks][2], qah[ks][3], bl0, bl1);
            MMA16816(C1, qah[ks][0], qah[ks][1], qah[ks][2], qah[ks][3], bl2, bl3);
        }

        // ---- epilogue: mask, exp, rowsum, Stile store; E stays in registers ----
        float e[2][4];
#pragma unroll
        for (int t = 0; t < 2; t++) {
            const float* C = t ? C1 : C0;
            int nb = kb0 + ln0 + t * 8 + tg * 2;
            uint2 m0 = *(const uint2*)(M + (size_t)(q0 + g) * S_LEN + nb);
            uint2 m1 = *(const uint2*)(M + (size_t)(q0 + g + 8) * S_LEN + nb);
            e[t][0] = m0.x ? 0.f : __expf(C[0] * 0.125f);
            e[t][1] = m0.y ? 0.f : __expf(C[1] * 0.125f);
            e[t][2] = m1.x ? 0.f : __expf(C[2] * 0.125f);
            e[t][3] = m1.y ? 0.f : __expf(C[3] * 0.125f);
            rs0 += e[t][0] + e[t][1];
            rs1 += e[t][2] + e[t][3];
            *(float2*)(smem + g * SSTRIDE + nb)       = make_float2(e[t][0], e[t][1]);
            *(float2*)(smem + (g + 8) * SSTRIDE + nb) = make_float2(e[t][2], e[t][3]);
        }

        // ---- E (C-frag) -> A-frag hi/lo in registers (identical layout) ----
        unsigned Ah[4], Al[4];
        cvt_hilo2(e[0][0], e[0][1], Ah[0], Al[0]);
        cvt_hilo2(e[0][2], e[0][3], Ah[1], Al[1]);
        cvt_hilo2(e[1][0], e[1][1], Ah[2], Al[2]);
        cvt_hilo2(e[1][2], e[1][3], Ah[3], Al[3]);

        // ---- PV: warp's 16 tokens x all 64 d (4 LDSM.x4.trans pairs) ----
#pragma unroll
        for (int jp = 0; jp < 4; jp++) {
            unsigned bh0, bh1, bh2, bh3, bl0, bl1, bl2, bl3;
            LDSM_X4_T(bh0, bh1, bh2, bh3, vh_base + jp * 32u);
            LDSM_X4_T(bl0, bl1, bl2, bl3, vl_base + jp * 32u);
            MMA16816(O[2*jp],     Ah[0], Ah[1], Ah[2], Ah[3], bh0, bh1);
            MMA16816(O[2*jp],     Al[0], Al[1], Al[2], Al[3], bh0, bh1);
            MMA16816(O[2*jp],     Ah[0], Ah[1], Ah[2], Ah[3], bl0, bl1);
            MMA16816(O[2*jp + 1], Ah[0], Ah[1], Ah[2], Ah[3], bh2, bh3);
            MMA16816(O[2*jp + 1], Al[0], Al[1], Al[2], Al[3], bh2, bh3);
            MMA16816(O[2*jp + 1], Ah[0], Ah[1], Ah[2], Ah[3], bl2, bl3);
        }
    }

    // ================= rowsums ================================================
    rs0 += __shfl_xor_sync(0xffffffff, rs0, 1);
    rs0 += __shfl_xor_sync(0xffffffff, rs0, 2);
    rs1 += __shfl_xor_sync(0xffffffff, rs1, 1);
    rs1 += __shfl_xor_sync(0xffffffff, rs1, 2);

    __syncthreads();   // last-stage LDSM reads complete before O-red overlays KH/KL

    if (tg == 0) {
        smem[OFF_PART + g * 8 + warp]       = rs0;
        smem[OFF_PART + (g + 8) * 8 + warp] = rs1;
    }
    {
        float* base = smem + OFF_RED + warp * (16 * REDSTR);
#pragma unroll
        for (int j = 0; j < 8; j++) {
            *(float2*)(base + g * REDSTR + j * 8 + 2 * tg)       = make_float2(O[j][0], O[j][1]);
            *(float2*)(base + (g + 8) * REDSTR + j * 8 + 2 * tg) = make_float2(O[j][2], O[j][3]);
        }
    }
    __syncthreads();

    if (tid < TQ) {
        float s = 0.f;
#pragma unroll
        for (int i = 0; i < 8; i++) s += smem[OFF_PART + tid * 8 + i];
        smem[OFF_INV + tid] = 1.0f / s;
    }
    __syncthreads();

    // ================= reduce O partials, write p_val =========================
    {
        int row = tid >> 4;
        int d0  = (tid & 15) * 4;
        float4 acc = make_float4(0.f, 0.f, 0.f, 0.f);
#pragma unroll
        for (int w = 0; w < 8; w++) {
            float4 v = *(const float4*)(smem + OFF_RED + w * (16 * REDSTR) + row * REDSTR + d0);
            acc.x += v.x; acc.y += v.y; acc.z += v.z; acc.w += v.w;
        }
        float inv = smem[OFF_INV + row];
        acc.x *= inv; acc.y *= inv; acc.z *= inv; acc.w *= inv;
        *(float4*)(p_val + ((size_t)bh * S_LEN + q0 + row) * D_DIM + d0) = acc;
    }

    // ================= write normalized p_attn ================================
    {
        float* out = p_attn + ((size_t)bh * S_LEN + q0) * S_LEN;
        const float4* Sf4 = (const float4*)smem;
#pragma unroll
        for (int i = 0; i < 32; i++) {
            int idx  = tid + i * 256;
            int row  = idx >> 9;
            int col4 = idx & 511;
            float4 v = Sf4[row * (SSTRIDE / 4) + col4];
            float inv = smem[OFF_INV + row];
            v.x *= inv; v.y *= inv; v.z *= inv; v.w *= inv;
            *((float4*)(out + (size_t)row * S_LEN) + col4) = v;
        }
    }
}

extern "C" void kernel_launch(void* const* d_in, const int* in_sizes, int n_in,
                              void* d_out, int out_size)
{
    const float*    Q = (const float*)d_in[0];
    const float*    K = (const float*)d_in[1];
    const float*    V = (const float*)d_in[2];
    const unsigned* M = (const unsigned*)d_in[3];

    float* p_val  = (float*)d_out;
    float* p_attn = (float*)d_out + (size_t)2 * 16 * 2048 * 64;

    const size_t smem_bytes = (size_t)SMEM_WORDS * sizeof(float);  // 210240
    cudaFuncSetAttribute(attn_flash_kernel,
                         cudaFuncAttributeMaxDynamicSharedMemorySize,
                         (int)smem_bytes);

    dim3 grid(S_LEN / TQ, 32);
    attn_flash_kernel<<<grid, 256, smem_bytes>>>(Q, K, V, M, p_val, p_attn);
}

// round 6
// speedup vs baseline: 5.3529x; 1.5230x over previous
#include <cuda_runtime.h>
#include <cuda_bf16.h>
#include <math.h>

#define S_LEN   2048
#define D_DIM   64
#define TQ      16
#define NBH     32
#define KVSTR   36        // u32 words per token row (32 data + 4 pad; mod 32 = 4 -> LDSM-clean)
#define REDSTR  68        // fp32 words per row in O-reduction area

// ---- main-kernel shared memory word offsets ----
#define OFF_Q     0                    // 16*68 = 1088
#define OFF_KH    1088                 // 128*36 = 4608
#define OFF_KL    5696
#define OFF_VH    10304
#define OFF_VL    14912
#define OFF_PART  19520                // 16*8 = 128
#define OFF_INV   19648                // 16
#define SMEM_WORDS 19664               // 78656 bytes -> 2 CTAs/SM
#define OFF_RED   OFF_KH               // O-reduction overlays KV stage: 8*16*68 = 8704 words

// ---- global scratch: pre-converted K/V (smem-identical layout) + rowsum invs ----
__device__ __align__(16) unsigned g_KH[(size_t)NBH * S_LEN * KVSTR];
__device__ __align__(16) unsigned g_KL[(size_t)NBH * S_LEN * KVSTR];
__device__ __align__(16) unsigned g_VH[(size_t)NBH * S_LEN * KVSTR];
__device__ __align__(16) unsigned g_VL[(size_t)NBH * S_LEN * KVSTR];
__device__ float g_inv[(size_t)NBH * S_LEN];

__device__ __forceinline__ void cvt_hilo2(float x, float y, unsigned &h, unsigned &l) {
    __nv_bfloat162 hh = __floats2bfloat162_rn(x, y);     // .x = x (low half)
    float rx = x - __bfloat162float(hh.x);
    float ry = y - __bfloat162float(hh.y);
    __nv_bfloat162 ll = __floats2bfloat162_rn(rx, ry);
    h = *reinterpret_cast<unsigned*>(&hh);
    l = *reinterpret_cast<unsigned*>(&ll);
}

#define MMA16816(C, A0, A1, A2, A3, B0, B1)                                        \
    asm volatile("mma.sync.aligned.m16n8k16.row.col.f32.bf16.bf16.f32 "            \
                 "{%0,%1,%2,%3},{%4,%5,%6,%7},{%8,%9},{%0,%1,%2,%3};\n"            \
                 : "+f"(C[0]), "+f"(C[1]), "+f"(C[2]), "+f"(C[3])                  \
                 : "r"(A0), "r"(A1), "r"(A2), "r"(A3), "r"(B0), "r"(B1))

#define LDSM_X4(R0, R1, R2, R3, ADDR)                                              \
    asm volatile("ldmatrix.sync.aligned.m8n8.x4.shared.b16 {%0,%1,%2,%3}, [%4];"  \
                 : "=r"(R0), "=r"(R1), "=r"(R2), "=r"(R3) : "r"(ADDR))

#define LDSM_X4_T(R0, R1, R2, R3, ADDR)                                            \
    asm volatile("ldmatrix.sync.aligned.m8n8.x4.trans.shared.b16 {%0,%1,%2,%3}, [%4];" \
                 : "=r"(R0), "=r"(R1), "=r"(R2), "=r"(R3) : "r"(ADDR))

#define CP_ASYNC16(SADDR, GPTR)                                                    \
    asm volatile("cp.async.cg.shared.global [%0], [%1], 16;\n" :: "r"(SADDR), "l"(GPTR))

// ===================== pre-pass: convert K,V -> bf16 hi/lo scratch ==============
__global__ void __launch_bounds__(256)
preconvert_kv(const float* __restrict__ K, const float* __restrict__ V)
{
    const int bh  = blockIdx.y;
    const int idx = blockIdx.x * 256 + threadIdx.x;   // 0..32767 : (token, c4)
    const int token = idx >> 4, c4 = idx & 15;
    const size_t tok = (size_t)bh * S_LEN + token;
    const size_t go  = tok * KVSTR + c4 * 2;

    unsigned h0, l0, h1, l1;
    float4 k = __ldg((const float4*)(K + tok * D_DIM) + c4);
    cvt_hilo2(k.x, k.y, h0, l0);
    cvt_hilo2(k.z, k.w, h1, l1);
    *(uint2*)&g_KH[go] = make_uint2(h0, h1);
    *(uint2*)&g_KL[go] = make_uint2(l0, l1);

    float4 v = __ldg((const float4*)(V + tok * D_DIM) + c4);
    cvt_hilo2(v.x, v.y, h0, l0);
    cvt_hilo2(v.z, v.w, h1, l1);
    *(uint2*)&g_VH[go] = make_uint2(h0, h1);
    *(uint2*)&g_VL[go] = make_uint2(l0, l1);
}

// ===================== main fused attention kernel ==============================
__global__ void __launch_bounds__(256, 2)
attn_flash_kernel(const float* __restrict__ Q,
                  const unsigned* __restrict__ M,
                  float* __restrict__ p_val,
                  float* __restrict__ p_attn)
{
    extern __shared__ float smem[];
    const unsigned smem_u32 = (unsigned)__cvta_generic_to_shared(smem);

    const int tid  = threadIdx.x;
    const int warp = tid >> 5;
    const int lane = tid & 31;
    const int g    = lane >> 2;
    const int tg   = lane & 3;
    const int bh   = blockIdx.y;
    const int q0   = blockIdx.x * TQ;
    const int ln0  = warp * 16;

    // ---- ldmatrix per-lane byte addresses (constant across stages) ----
    const int qk_row  = ln0 + ((lane >> 4) << 3) + (lane & 7);
    const unsigned qk_off = (unsigned)(qk_row * KVSTR + (((lane >> 3) & 1) << 2)) * 4u;
    const unsigned kh_base = smem_u32 + OFF_KH * 4u + qk_off;
    const unsigned kl_base = smem_u32 + OFF_KL * 4u + qk_off;
    const int pv_row  = ln0 + (((lane >> 3) & 1) << 3) + (lane & 7);
    const unsigned pv_off = (unsigned)(pv_row * KVSTR + ((lane >> 4) << 2)) * 4u;
    const unsigned vh_base = smem_u32 + OFF_VH * 4u + pv_off;
    const unsigned vl_base = smem_u32 + OFF_VL * 4u + pv_off;

    // ================= Q tile -> smem -> A fragments (hi/lo, 4 k-steps) ========
    {
        int row = tid >> 4, c4 = tid & 15;
        float4 qv = __ldg((const float4*)(Q + ((size_t)bh * S_LEN + q0 + row) * D_DIM) + c4);
        *((float4*)(smem + OFF_Q + row * 68 + c4 * 4)) = qv;
    }
    __syncthreads();

    unsigned qah[4][4], qal[4][4];
#pragma unroll
    for (int ks = 0; ks < 4; ks++) {
        int c = ks * 16 + tg * 2;
        float2 x0 = *(const float2*)(smem + OFF_Q + g * 68 + c);
        float2 x1 = *(const float2*)(smem + OFF_Q + (g + 8) * 68 + c);
        float2 x2 = *(const float2*)(smem + OFF_Q + g * 68 + c + 8);
        float2 x3 = *(const float2*)(smem + OFF_Q + (g + 8) * 68 + c + 8);
        cvt_hilo2(x0.x, x0.y, qah[ks][0], qal[ks][0]);
        cvt_hilo2(x1.x, x1.y, qah[ks][1], qal[ks][1]);
        cvt_hilo2(x2.x, x2.y, qah[ks][2], qal[ks][2]);
        cvt_hilo2(x3.x, x3.y, qah[ks][3], qal[ks][3]);
    }

    float rs0 = 0.f, rs1 = 0.f;
    float O[8][4];
#pragma unroll
    for (int j = 0; j < 8; j++) { O[j][0] = O[j][1] = O[j][2] = O[j][3] = 0.f; }

    // p_attn row pointers for this thread's epilogue stores
    float* pa_g  = p_attn + ((size_t)bh * S_LEN + q0 + g) * S_LEN;
    float* pa_g8 = pa_g + 8 * S_LEN;
    const unsigned* mr_g  = M + (size_t)(q0 + g) * S_LEN;
    const unsigned* mr_g8 = M + (size_t)(q0 + g + 8) * S_LEN;

    const size_t bh_base = (size_t)bh * S_LEN * KVSTR;

    // =================== fused main loop over 16 stages of 128 tokens ==========
    for (int st = 0; st < 16; st++) {
        const int kb0 = st * 128;
        __syncthreads();   // previous stage's LDSM reads complete

        // ---- stage K/V hi/lo: pure 73.7 KB cp.async copy (pre-converted) ----
        {
            const size_t sb = bh_base + (size_t)kb0 * KVSTR;   // 4608 words = 1152 uint4
            const uint4* s0 = (const uint4*)(g_KH + sb);
            const uint4* s1 = (const uint4*)(g_KL + sb);
            const uint4* s2 = (const uint4*)(g_VH + sb);
            const uint4* s3 = (const uint4*)(g_VL + sb);
            for (int i = tid; i < 1152; i += 256) {
                unsigned off16 = (unsigned)i * 16u;
                CP_ASYNC16(smem_u32 + OFF_KH * 4u + off16, s0 + i);
                CP_ASYNC16(smem_u32 + OFF_KL * 4u + off16, s1 + i);
                CP_ASYNC16(smem_u32 + OFF_VH * 4u + off16, s2 + i);
                CP_ASYNC16(smem_u32 + OFF_VL * 4u + off16, s3 + i);
            }
            asm volatile("cp.async.commit_group;\n");
            asm volatile("cp.async.wait_group 0;\n" ::: "memory");
        }
        __syncthreads();

        // ---- QK^T for this warp's 16 tokens (two n-tiles), 3-term hi/lo ----
        float C0[4] = {0.f, 0.f, 0.f, 0.f};
        float C1[4] = {0.f, 0.f, 0.f, 0.f};
#pragma unroll
        for (int ks = 0; ks < 4; ks++) {
            unsigned bh0, bh1, bh2, bh3, bl0, bl1, bl2, bl3;
            LDSM_X4(bh0, bh1, bh2, bh3, kh_base + ks * 32u);
            LDSM_X4(bl0, bl1, bl2, bl3, kl_base + ks * 32u);
            MMA16816(C0, qah[ks][0], qah[ks][1], qah[ks][2], qah[ks][3], bh0, bh1);
            MMA16816(C1, qah[ks][0], qah[ks][1], qah[ks][2], qah[ks][3], bh2, bh3);
            MMA16816(C0, qal[ks][0], qal[ks][1], qal[ks][2], qal[ks][3], bh0, bh1);
            MMA16816(C1, qal[ks][0], qal[ks][1], qal[ks][2], qal[ks][3], bh2, bh3);
            MMA16816(C0, qah[ks][0], qah[ks][1], qah[ks][2], qah[ks][3], bl0, bl1);
            MMA16816(C1, qah[ks][0], qah[ks][1], qah[ks][2], qah[ks][3], bl2, bl3);
        }

        // ---- epilogue: mask, exp, rowsum; unnormalized exp -> p_attn gmem ----
        float e[2][4];
#pragma unroll
        for (int t = 0; t < 2; t++) {
            const float* C = t ? C1 : C0;
            int nb = kb0 + ln0 + t * 8 + tg * 2;
            uint2 m0 = *(const uint2*)(mr_g  + nb);
            uint2 m1 = *(const uint2*)(mr_g8 + nb);
            e[t][0] = m0.x ? 0.f : __expf(C[0] * 0.125f);
            e[t][1] = m0.y ? 0.f : __expf(C[1] * 0.125f);
            e[t][2] = m1.x ? 0.f : __expf(C[2] * 0.125f);
            e[t][3] = m1.y ? 0.f : __expf(C[3] * 0.125f);
            rs0 += e[t][0] + e[t][1];
            rs1 += e[t][2] + e[t][3];
            *(float2*)(pa_g  + nb) = make_float2(e[t][0], e[t][1]);
            *(float2*)(pa_g8 + nb) = make_float2(e[t][2], e[t][3]);
        }

        // ---- E (C-frag) -> A-frag hi/lo in registers (identical layout) ----
        unsigned Ah[4], Al[4];
        cvt_hilo2(e[0][0], e[0][1], Ah[0], Al[0]);
        cvt_hilo2(e[0][2], e[0][3], Ah[1], Al[1]);
        cvt_hilo2(e[1][0], e[1][1], Ah[2], Al[2]);
        cvt_hilo2(e[1][2], e[1][3], Ah[3], Al[3]);

        // ---- PV: warp's 16 tokens x all 64 d (4 LDSM.x4.trans pairs) ----
#pragma unroll
        for (int jp = 0; jp < 4; jp++) {
            unsigned bh0, bh1, bh2, bh3, bl0, bl1, bl2, bl3;
            LDSM_X4_T(bh0, bh1, bh2, bh3, vh_base + jp * 32u);
            LDSM_X4_T(bl0, bl1, bl2, bl3, vl_base + jp * 32u);
            MMA16816(O[2*jp],     Ah[0], Ah[1], Ah[2], Ah[3], bh0, bh1);
            MMA16816(O[2*jp],     Al[0], Al[1], Al[2], Al[3], bh0, bh1);
            MMA16816(O[2*jp],     Ah[0], Ah[1], Ah[2], Ah[3], bl0, bl1);
            MMA16816(O[2*jp + 1], Ah[0], Ah[1], Ah[2], Ah[3], bh2, bh3);
            MMA16816(O[2*jp + 1], Al[0], Al[1], Al[2], Al[3], bh2, bh3);
            MMA16816(O[2*jp + 1], Ah[0], Ah[1], Ah[2], Ah[3], bl2, bl3);
        }
    }

    // ================= rowsums ================================================
    rs0 += __shfl_xor_sync(0xffffffff, rs0, 1);
    rs0 += __shfl_xor_sync(0xffffffff, rs0, 2);
    rs1 += __shfl_xor_sync(0xffffffff, rs1, 1);
    rs1 += __shfl_xor_sync(0xffffffff, rs1, 2);

    __syncthreads();   // last-stage LDSM reads done before O-red overlays KV

    if (tg == 0) {
        smem[OFF_PART + g * 8 + warp]       = rs0;
        smem[OFF_PART + (g + 8) * 8 + warp] = rs1;
    }
    {
        float* base = smem + OFF_RED + warp * (16 * REDSTR);
#pragma unroll
        for (int j = 0; j < 8; j++) {
            *(float2*)(base + g * REDSTR + j * 8 + 2 * tg)       = make_float2(O[j][0], O[j][1]);
            *(float2*)(base + (g + 8) * REDSTR + j * 8 + 2 * tg) = make_float2(O[j][2], O[j][3]);
        }
    }
    __syncthreads();

    if (tid < TQ) {
        float s = 0.f;
#pragma unroll
        for (int i = 0; i < 8; i++) s += smem[OFF_PART + tid * 8 + i];
        float iv = 1.0f / s;
        smem[OFF_INV + tid] = iv;
        g_inv[(size_t)bh * S_LEN + q0 + tid] = iv;     // for the normalize pass
    }
    __syncthreads();

    // ================= reduce O partials, write p_val =========================
    {
        int row = tid >> 4;
        int d0  = (tid & 15) * 4;
        float4 acc = make_float4(0.f, 0.f, 0.f, 0.f);
#pragma unroll
        for (int w = 0; w < 8; w++) {
            float4 v = *(const float4*)(smem + OFF_RED + w * (16 * REDSTR) + row * REDSTR + d0);
            acc.x += v.x; acc.y += v.y; acc.z += v.z; acc.w += v.w;
        }
        float inv = smem[OFF_INV + row];
        acc.x *= inv; acc.y *= inv; acc.z *= inv; acc.w *= inv;
        *(float4*)(p_val + ((size_t)bh * S_LEN + q0 + row) * D_DIM + d0) = acc;
    }
}

// ===================== normalize pass: p_attn *= inv[row] =======================
__global__ void __launch_bounds__(256)
normalize_pattn(float* __restrict__ p_attn)
{
    float4* p4 = (float4*)p_attn;
    const size_t stride = (size_t)gridDim.x * 256;
    size_t i4 = (size_t)blockIdx.x * 256 + threadIdx.x;
#pragma unroll
    for (int it = 0; it < 8; it++) {
        unsigned row = (unsigned)(i4 >> 9);            // 512 float4 per S-row
        float inv = __ldg(&g_inv[row]);
        float4 v = p4[i4];
        v.x *= inv; v.y *= inv; v.z *= inv; v.w *= inv;
        p4[i4] = v;
        i4 += stride;
    }
}

extern "C" void kernel_launch(void* const* d_in, const int* in_sizes, int n_in,
                              void* d_out, int out_size)
{
    const float*    Q = (const float*)d_in[0];
    const float*    K = (const float*)d_in[1];
    const float*    V = (const float*)d_in[2];
    const unsigned* M = (const unsigned*)d_in[3];

    float* p_val  = (float*)d_out;
    float* p_attn = (float*)d_out + (size_t)2 * 16 * 2048 * 64;

    const size_t smem_bytes = (size_t)SMEM_WORDS * sizeof(float);  // 78656
    cudaFuncSetAttribute(attn_flash_kernel,
                         cudaFuncAttributeMaxDynamicSharedMemorySize,
                         (int)smem_bytes);

    preconvert_kv<<<dim3(128, NBH), 256>>>(K, V);
    attn_flash_kernel<<<dim3(S_LEN / TQ, NBH), 256, smem_bytes>>>(Q, M, p_val, p_attn);
    normalize_pattn<<<16384, 256>>>(p_attn);   // 16384*256*8 float4 = whole p_attn
}

// round 7
// speedup vs baseline: 5.4574x; 1.0195x over previous
#include <cuda_runtime.h>
#include <cuda_bf16.h>
#include <math.h>

#define S_LEN   2048
#define D_DIM   64
#define TQ      32
#define NBH     32
#define KVSTR   36        // u32 words per token row (32 data + 4 pad; LDSM-clean)
#define REDSTR  68

// ---- main-kernel shared memory word offsets ----
#define OFF_Q    0                     // 32*68 = 2176
#define ARR_W    4608                  // 128 tokens * 36 words
#define BUF_W    (4*ARR_W)             // KH,KL,VH,VL = 18432 words per buffer
#define OFF_BUF  2176                  // two buffers: 2*18432 = 36864
#define OFF_PART (OFF_BUF + 2*BUF_W)   // 39040 : 32*8
#define OFF_INV  (OFF_PART + 256)      // 39296 : 32
#define SMEM_WORDS (OFF_INV + 32)      // 39328 words = 157312 bytes
#define OFF_RED  OFF_BUF               // O-reduction overlay: 8*32*68 = 17408 words

// ---- global scratch ----
__device__ __align__(16) unsigned g_KH[(size_t)NBH * S_LEN * KVSTR];
__device__ __align__(16) unsigned g_KL[(size_t)NBH * S_LEN * KVSTR];
__device__ __align__(16) unsigned g_VH[(size_t)NBH * S_LEN * KVSTR];
__device__ __align__(16) unsigned g_VL[(size_t)NBH * S_LEN * KVSTR];
__device__ float    g_inv[(size_t)NBH * S_LEN];
__device__ unsigned g_mpack[(size_t)S_LEN * (S_LEN / 32)];   // 1 bit per mask elem

__device__ __forceinline__ void cvt_hilo2(float x, float y, unsigned &h, unsigned &l) {
    __nv_bfloat162 hh = __floats2bfloat162_rn(x, y);
    float rx = x - __bfloat162float(hh.x);
    float ry = y - __bfloat162float(hh.y);
    __nv_bfloat162 ll = __floats2bfloat162_rn(rx, ry);
    h = *reinterpret_cast<unsigned*>(&hh);
    l = *reinterpret_cast<unsigned*>(&ll);
}

#define MMA16816(C, A0, A1, A2, A3, B0, B1)                                        \
    asm volatile("mma.sync.aligned.m16n8k16.row.col.f32.bf16.bf16.f32 "            \
                 "{%0,%1,%2,%3},{%4,%5,%6,%7},{%8,%9},{%0,%1,%2,%3};\n"            \
                 : "+f"(C[0]), "+f"(C[1]), "+f"(C[2]), "+f"(C[3])                  \
                 : "r"(A0), "r"(A1), "r"(A2), "r"(A3), "r"(B0), "r"(B1))

#define LDSM_X4(R0, R1, R2, R3, ADDR)                                              \
    asm volatile("ldmatrix.sync.aligned.m8n8.x4.shared.b16 {%0,%1,%2,%3}, [%4];"  \
                 : "=r"(R0), "=r"(R1), "=r"(R2), "=r"(R3) : "r"(ADDR))

#define LDSM_X4_T(R0, R1, R2, R3, ADDR)                                            \
    asm volatile("ldmatrix.sync.aligned.m8n8.x4.trans.shared.b16 {%0,%1,%2,%3}, [%4];" \
                 : "=r"(R0), "=r"(R1), "=r"(R2), "=r"(R3) : "r"(ADDR))

#define CP_ASYNC16(SADDR, GPTR)                                                    \
    asm volatile("cp.async.cg.shared.global [%0], [%1], 16;\n" :: "r"(SADDR), "l"(GPTR))

// ===================== pre-pass 1: convert K,V -> bf16 hi/lo scratch ============
__global__ void __launch_bounds__(256)
preconvert_kv(const float* __restrict__ K, const float* __restrict__ V)
{
    const int bh  = blockIdx.y;
    const int idx = blockIdx.x * 256 + threadIdx.x;
    const int token = idx >> 4, c4 = idx & 15;
    const size_t tok = (size_t)bh * S_LEN + token;
    const size_t go  = tok * KVSTR + c4 * 2;

    unsigned h0, l0, h1, l1;
    float4 k = __ldg((const float4*)(K + tok * D_DIM) + c4);
    cvt_hilo2(k.x, k.y, h0, l0);
    cvt_hilo2(k.z, k.w, h1, l1);
    *(uint2*)&g_KH[go] = make_uint2(h0, h1);
    *(uint2*)&g_KL[go] = make_uint2(l0, l1);

    float4 v = __ldg((const float4*)(V + tok * D_DIM) + c4);
    cvt_hilo2(v.x, v.y, h0, l0);
    cvt_hilo2(v.z, v.w, h1, l1);
    *(uint2*)&g_VH[go] = make_uint2(h0, h1);
    *(uint2*)&g_VL[go] = make_uint2(l0, l1);
}

// ===================== pre-pass 2: pack mask to 1 bit/elem ======================
__global__ void __launch_bounds__(256)
pack_mask(const unsigned* __restrict__ M)
{
    const int lane = threadIdx.x & 31;
    const int wglob = (blockIdx.x * 256 + threadIdx.x) >> 5;   // global warp id
    const int nwarps = (gridDim.x * 256) >> 5;
    for (int w = wglob; w < S_LEN * (S_LEN / 32); w += nwarps) {
        unsigned bit = (M[(size_t)w * 32 + lane] != 0u) ? 1u : 0u;
        unsigned word = __ballot_sync(0xffffffffu, bit);
        if (lane == 0) g_mpack[w] = word;
    }
}

// ===================== main fused attention kernel ==============================
__global__ void __launch_bounds__(256, 1)
attn_flash_kernel(const float* __restrict__ Q,
                  float* __restrict__ p_val,
                  float* __restrict__ p_attn)
{
    extern __shared__ float smem[];
    const unsigned smem_u32 = (unsigned)__cvta_generic_to_shared(smem);

    const int tid  = threadIdx.x;
    const int warp = tid >> 5;
    const int lane = tid & 31;
    const int g    = lane >> 2;
    const int tg   = lane & 3;
    const int bh   = blockIdx.y;
    const int q0   = blockIdx.x * TQ;
    const int ln0  = warp * 16;

    // ---- ldmatrix per-lane byte addresses (buffer 0) ----
    const int qk_row  = ln0 + ((lane >> 4) << 3) + (lane & 7);
    const unsigned qk_off = (unsigned)(qk_row * KVSTR + (((lane >> 3) & 1) << 2)) * 4u;
    const unsigned kh_base = smem_u32 + (OFF_BUF + 0 * ARR_W) * 4u + qk_off;
    const unsigned kl_base = smem_u32 + (OFF_BUF + 1 * ARR_W) * 4u + qk_off;
    const int pv_row  = ln0 + (((lane >> 3) & 1) << 3) + (lane & 7);
    const unsigned pv_off = (unsigned)(pv_row * KVSTR + ((lane >> 4) << 2)) * 4u;
    const unsigned vh_base = smem_u32 + (OFF_BUF + 2 * ARR_W) * 4u + pv_off;
    const unsigned vl_base = smem_u32 + (OFF_BUF + 3 * ARR_W) * 4u + pv_off;

    // ================= Q tile (32 rows) -> smem -> A fragments =================
    {
#pragma unroll
        for (int i = 0; i < 2; i++) {
            int idx = tid + i * 256;
            int row = idx >> 4, c4 = idx & 15;
            float4 qv = __ldg((const float4*)(Q + ((size_t)bh * S_LEN + q0 + row) * D_DIM) + c4);
            *((float4*)(smem + OFF_Q + row * 68 + c4 * 4)) = qv;
        }
    }
    __syncthreads();

    unsigned qah[2][4][4], qal[2][4][4];
#pragma unroll
    for (int m = 0; m < 2; m++) {
        int r0 = m * 16 + g, r1 = m * 16 + g + 8;
#pragma unroll
        for (int ks = 0; ks < 4; ks++) {
            int c = ks * 16 + tg * 2;
            float2 x0 = *(const float2*)(smem + OFF_Q + r0 * 68 + c);
            float2 x1 = *(const float2*)(smem + OFF_Q + r1 * 68 + c);
            float2 x2 = *(const float2*)(smem + OFF_Q + r0 * 68 + c + 8);
            float2 x3 = *(const float2*)(smem + OFF_Q + r1 * 68 + c + 8);
            cvt_hilo2(x0.x, x0.y, qah[m][ks][0], qal[m][ks][0]);
            cvt_hilo2(x1.x, x1.y, qah[m][ks][1], qal[m][ks][1]);
            cvt_hilo2(x2.x, x2.y, qah[m][ks][2], qal[m][ks][2]);
            cvt_hilo2(x3.x, x3.y, qah[m][ks][3], qal[m][ks][3]);
        }
    }

    float rs[4] = {0.f, 0.f, 0.f, 0.f};
    float O[16][4];
#pragma unroll
    for (int j = 0; j < 16; j++) { O[j][0] = O[j][1] = O[j][2] = O[j][3] = 0.f; }

    // mask word pointers (one broadcast word per row per stage) and p_attn rows
    const unsigned* mp[4];
    float* pa[4];
#pragma unroll
    for (int r = 0; r < 4; r++) {
        int row = (r >> 1) * 16 + g + (r & 1) * 8;    // g, g+8, 16+g, 24+g
        mp[r] = g_mpack + (size_t)(q0 + row) * 64 + (warp >> 1);
        pa[r] = p_attn + ((size_t)bh * S_LEN + q0 + row) * S_LEN;
    }
    const unsigned posbase = (warp & 1) * 16;
    const size_t bh_base = (size_t)bh * S_LEN * KVSTR;

    // ---- prologue: issue stage 0 loads ----
    {
        const size_t sb = bh_base;
        for (int i = tid; i < ARR_W / 4; i += 256) {
            unsigned so = (unsigned)(OFF_BUF * 4 + i * 16);
            CP_ASYNC16(smem_u32 + so,                 (const uint4*)(g_KH + sb) + i);
            CP_ASYNC16(smem_u32 + so + ARR_W * 4,     (const uint4*)(g_KL + sb) + i);
            CP_ASYNC16(smem_u32 + so + 2 * ARR_W * 4, (const uint4*)(g_VH + sb) + i);
            CP_ASYNC16(smem_u32 + so + 3 * ARR_W * 4, (const uint4*)(g_VL + sb) + i);
        }
        asm volatile("cp.async.commit_group;\n");
    }

    // =================== pipelined main loop: 16 stages of 128 tokens ==========
    for (int st = 0; st < 16; st++) {
        const int kb0 = st * 128;
        const unsigned bufoff = (unsigned)(st & 1) * (BUF_W * 4);

        asm volatile("cp.async.wait_group 0;\n" ::: "memory");
        __syncthreads();   // stage-st data visible to all; prev compute done

        // ---- prefetch stage st+1 into the other buffer ----
        if (st < 15) {
            const size_t sb = bh_base + (size_t)(kb0 + 128) * KVSTR;
            const unsigned dst = (unsigned)(OFF_BUF * 4) + (unsigned)((st + 1) & 1) * (BUF_W * 4);
            for (int i = tid; i < ARR_W / 4; i += 256) {
                unsigned so = dst + (unsigned)i * 16u;
                CP_ASYNC16(smem_u32 + so,                 (const uint4*)(g_KH + sb) + i);
                CP_ASYNC16(smem_u32 + so + ARR_W * 4,     (const uint4*)(g_KL + sb) + i);
                CP_ASYNC16(smem_u32 + so + 2 * ARR_W * 4, (const uint4*)(g_VH + sb) + i);
                CP_ASYNC16(smem_u32 + so + 3 * ARR_W * 4, (const uint4*)(g_VL + sb) + i);
            }
            asm volatile("cp.async.commit_group;\n");
        }

        // ---- QK^T: 2 M-tiles x warp's 16 tokens, 3-term hi/lo ----
        float C00[4] = {0,0,0,0}, C01[4] = {0,0,0,0};
        float C10[4] = {0,0,0,0}, C11[4] = {0,0,0,0};
#pragma unroll
        for (int ks = 0; ks < 4; ks++) {
            unsigned b0, b1, b2, b3, l0, l1, l2, l3;
            LDSM_X4(b0, b1, b2, b3, kh_base + bufoff + ks * 32u);
            LDSM_X4(l0, l1, l2, l3, kl_base + bufoff + ks * 32u);
            MMA16816(C00, qah[0][ks][0], qah[0][ks][1], qah[0][ks][2], qah[0][ks][3], b0, b1);
            MMA16816(C01, qah[0][ks][0], qah[0][ks][1], qah[0][ks][2], qah[0][ks][3], b2, b3);
            MMA16816(C10, qah[1][ks][0], qah[1][ks][1], qah[1][ks][2], qah[1][ks][3], b0, b1);
            MMA16816(C11, qah[1][ks][0], qah[1][ks][1], qah[1][ks][2], qah[1][ks][3], b2, b3);
            MMA16816(C00, qal[0][ks][0], qal[0][ks][1], qal[0][ks][2], qal[0][ks][3], b0, b1);
            MMA16816(C01, qal[0][ks][0], qal[0][ks][1], qal[0][ks][2], qal[0][ks][3], b2, b3);
            MMA16816(C10, qal[1][ks][0], qal[1][ks][1], qal[1][ks][2], qal[1][ks][3], b0, b1);
            MMA16816(C11, qal[1][ks][0], qal[1][ks][1], qal[1][ks][2], qal[1][ks][3], b2, b3);
            MMA16816(C00, qah[0][ks][0], qah[0][ks][1], qah[0][ks][2], qah[0][ks][3], l0, l1);
            MMA16816(C01, qah[0][ks][0], qah[0][ks][1], qah[0][ks][2], qah[0][ks][3], l2, l3);
            MMA16816(C10, qah[1][ks][0], qah[1][ks][1], qah[1][ks][2], qah[1][ks][3], l0, l1);
            MMA16816(C11, qah[1][ks][0], qah[1][ks][1], qah[1][ks][2], qah[1][ks][3], l2, l3);
        }

        // ---- epilogue: mask(bit), exp, rowsum; unnormalized exp -> p_attn ----
        unsigned mw0 = __ldg(mp[0] + st * 4);
        unsigned mw1 = __ldg(mp[1] + st * 4);
        unsigned mw2 = __ldg(mp[2] + st * 4);
        unsigned mw3 = __ldg(mp[3] + st * 4);
        float e[2][2][4];
#pragma unroll
        for (int m = 0; m < 2; m++) {
            unsigned ma = m ? mw2 : mw0;   // row m*16+g
            unsigned mb = m ? mw3 : mw1;   // row m*16+g+8
#pragma unroll
            for (int t = 0; t < 2; t++) {
                const float* C = m ? (t ? C11 : C10) : (t ? C01 : C00);
                int nb = kb0 + ln0 + t * 8 + tg * 2;
                unsigned sh = posbase + t * 8 + tg * 2;
                float* E = e[m][t];
                E[0] = ((ma >> sh) & 1u)       ? 0.f : __expf(C[0] * 0.125f);
                E[1] = ((ma >> (sh + 1)) & 1u) ? 0.f : __expf(C[1] * 0.125f);
                E[2] = ((mb >> sh) & 1u)       ? 0.f : __expf(C[2] * 0.125f);
                E[3] = ((mb >> (sh + 1)) & 1u) ? 0.f : __expf(C[3] * 0.125f);
                rs[2 * m]     += E[0] + E[1];
                rs[2 * m + 1] += E[2] + E[3];
                *(float2*)(pa[2 * m]     + nb) = make_float2(E[0], E[1]);
                *(float2*)(pa[2 * m + 1] + nb) = make_float2(E[2], E[3]);
            }
        }

        // ---- E -> A-frag hi/lo in registers (C-frag layout == A-frag layout) ----
        unsigned Ah[2][4], Al[2][4];
#pragma unroll
        for (int m = 0; m < 2; m++) {
            cvt_hilo2(e[m][0][0], e[m][0][1], Ah[m][0], Al[m][0]);
            cvt_hilo2(e[m][0][2], e[m][0][3], Ah[m][1], Al[m][1]);
            cvt_hilo2(e[m][1][0], e[m][1][1], Ah[m][2], Al[m][2]);
            cvt_hilo2(e[m][1][2], e[m][1][3], Ah[m][3], Al[m][3]);
        }

        // ---- PV: warp's 16 tokens x all 64 d (4 LDSM.x4.trans pairs) ----
#pragma unroll
        for (int jp = 0; jp < 4; jp++) {
            unsigned b0, b1, b2, b3, l0, l1, l2, l3;
            LDSM_X4_T(b0, b1, b2, b3, vh_base + bufoff + jp * 32u);
            LDSM_X4_T(l0, l1, l2, l3, vl_base + bufoff + jp * 32u);
#pragma unroll
            for (int m = 0; m < 2; m++) {
                float* Oa = O[m * 8 + 2 * jp];
                float* Ob = O[m * 8 + 2 * jp + 1];
                MMA16816(Oa, Ah[m][0], Ah[m][1], Ah[m][2], Ah[m][3], b0, b1);
                MMA16816(Oa, Al[m][0], Al[m][1], Al[m][2], Al[m][3], b0, b1);
                MMA16816(Oa, Ah[m][0], Ah[m][1], Ah[m][2], Ah[m][3], l0, l1);
                MMA16816(Ob, Ah[m][0], Ah[m][1], Ah[m][2], Ah[m][3], b2, b3);
                MMA16816(Ob, Al[m][0], Al[m][1], Al[m][2], Al[m][3], b2, b3);
                MMA16816(Ob, Ah[m][0], Ah[m][1], Ah[m][2], Ah[m][3], l2, l3);
            }
        }
    }

    // ================= rowsums ================================================
#pragma unroll
    for (int r = 0; r < 4; r++) {
        rs[r] += __shfl_xor_sync(0xffffffff, rs[r], 1);
        rs[r] += __shfl_xor_sync(0xffffffff, rs[r], 2);
    }

    __syncthreads();   // last-stage LDSM reads done before O-red overlays buffers

    if (tg == 0) {
#pragma unroll
        for (int r = 0; r < 4; r++) {
            int row = (r >> 1) * 16 + g + (r & 1) * 8;
            smem[OFF_PART + row * 8 + warp] = rs[r];
        }
    }
    {
        float* base = smem + OFF_RED + warp * (32 * REDSTR);
#pragma unroll
        for (int m = 0; m < 2; m++) {
            int r0 = m * 16 + g, r1 = m * 16 + g + 8;
#pragma unroll
            for (int j = 0; j < 8; j++) {
                const float* Oj = O[m * 8 + j];
                *(float2*)(base + r0 * REDSTR + j * 8 + 2 * tg) = make_float2(Oj[0], Oj[1]);
                *(float2*)(base + r1 * REDSTR + j * 8 + 2 * tg) = make_float2(Oj[2], Oj[3]);
            }
        }
    }
    __syncthreads();

    if (tid < TQ) {
        float s = 0.f;
#pragma unroll
        for (int i = 0; i < 8; i++) s += smem[OFF_PART + tid * 8 + i];
        float iv = 1.0f / s;
        smem[OFF_INV + tid] = iv;
        g_inv[(size_t)bh * S_LEN + q0 + tid] = iv;
    }
    __syncthreads();

    // ================= reduce O partials, write p_val =========================
#pragma unroll
    for (int it = 0; it < 2; it++) {
        int item = tid + it * 256;       // 0..511
        int row = item >> 4;
        int d0  = (item & 15) * 4;
        float4 acc = make_float4(0.f, 0.f, 0.f, 0.f);
#pragma unroll
        for (int w = 0; w < 8; w++) {
            float4 v = *(const float4*)(smem + OFF_RED + w * (32 * REDSTR) + row * REDSTR + d0);
            acc.x += v.x; acc.y += v.y; acc.z += v.z; acc.w += v.w;
        }
        float inv = smem[OFF_INV + row];
        acc.x *= inv; acc.y *= inv; acc.z *= inv; acc.w *= inv;
        *(float4*)(p_val + ((size_t)bh * S_LEN + q0 + row) * D_DIM + d0) = acc;
    }
}

// ===================== normalize pass: p_attn *= inv[row] =======================
__global__ void __launch_bounds__(256)
normalize_pattn(float* __restrict__ p_attn)
{
    float4* p4 = (float4*)p_attn;
    const size_t stride = (size_t)gridDim.x * 256;
    size_t i4 = (size_t)blockIdx.x * 256 + threadIdx.x;
#pragma unroll
    for (int it = 0; it < 8; it++) {
        unsigned row = (unsigned)(i4 >> 9);
        float inv = __ldg(&g_inv[row]);
        float4 v = p4[i4];
        v.x *= inv; v.y *= inv; v.z *= inv; v.w *= inv;
        p4[i4] = v;
        i4 += stride;
    }
}

extern "C" void kernel_launch(void* const* d_in, const int* in_sizes, int n_in,
                              void* d_out, int out_size)
{
    const float*    Q = (const float*)d_in[0];
    const float*    K = (const float*)d_in[1];
    const float*    V = (const float*)d_in[2];
    const unsigned* M = (const unsigned*)d_in[3];

    float* p_val  = (float*)d_out;
    float* p_attn = (float*)d_out + (size_t)2 * 16 * 2048 * 64;

    const size_t smem_bytes = (size_t)SMEM_WORDS * sizeof(float);  // 157312
    cudaFuncSetAttribute(attn_flash_kernel,
                         cudaFuncAttributeMaxDynamicSharedMemorySize,
                         (int)smem_bytes);

    preconvert_kv<<<dim3(128, NBH), 256>>>(K, V);
    pack_mask<<<512, 256>>>(M);
    attn_flash_kernel<<<dim3(S_LEN / TQ, NBH), 256, smem_bytes>>>(Q, p_val, p_attn);
    normalize_pattn<<<16384, 256>>>(p_attn);
}

// round 8
// speedup vs baseline: 5.4749x; 1.0032x over previous
#include <cuda_runtime.h>
#include <cuda_bf16.h>
#include <math.h>

#define S_LEN   2048
#define D_DIM   64
#define TQ      32
#define NBH     32
#define KVSTR   36        // u32 words per token row (32 data + 4 pad; LDSM-clean)
#define REDSTR  68

// ---- main-kernel shared memory word offsets ----
#define OFF_Q    0                     // 32*68 = 2176
#define ARR_W    4608                  // 128 tokens * 36 words
#define BUF_W    (4*ARR_W)             // KH,KL,VH,VL = 18432 words per buffer
#define OFF_BUF  2176                  // two buffers: 2*18432 = 36864
#define OFF_PART (OFF_BUF + 2*BUF_W)   // 39040 : 32*8
#define OFF_INV  (OFF_PART + 256)      // 39296 : 32
#define SMEM_WORDS (OFF_INV + 32)      // 39328 words = 157312 bytes
#define OFF_RED  OFF_BUF               // O-reduction overlay: 8*32*68 = 17408 words

// ---- global scratch ----
__device__ __align__(16) unsigned g_KH[(size_t)NBH * S_LEN * KVSTR];
__device__ __align__(16) unsigned g_KL[(size_t)NBH * S_LEN * KVSTR];
__device__ __align__(16) unsigned g_VH[(size_t)NBH * S_LEN * KVSTR];
__device__ __align__(16) unsigned g_VL[(size_t)NBH * S_LEN * KVSTR];
__device__ float    g_inv[(size_t)NBH * S_LEN];
__device__ unsigned g_mpack[(size_t)S_LEN * (S_LEN / 32)];   // 1 bit per mask elem

__device__ __forceinline__ void cvt_hilo2(float x, float y, unsigned &h, unsigned &l) {
    __nv_bfloat162 hh = __floats2bfloat162_rn(x, y);
    float rx = x - __bfloat162float(hh.x);
    float ry = y - __bfloat162float(hh.y);
    __nv_bfloat162 ll = __floats2bfloat162_rn(rx, ry);
    h = *reinterpret_cast<unsigned*>(&hh);
    l = *reinterpret_cast<unsigned*>(&ll);
}

#define MMA16816(C, A0, A1, A2, A3, B0, B1)                                        \
    asm volatile("mma.sync.aligned.m16n8k16.row.col.f32.bf16.bf16.f32 "            \
                 "{%0,%1,%2,%3},{%4,%5,%6,%7},{%8,%9},{%0,%1,%2,%3};\n"            \
                 : "+f"(C[0]), "+f"(C[1]), "+f"(C[2]), "+f"(C[3])                  \
                 : "r"(A0), "r"(A1), "r"(A2), "r"(A3), "r"(B0), "r"(B1))

#define LDSM_X4(R0, R1, R2, R3, ADDR)                                              \
    asm volatile("ldmatrix.sync.aligned.m8n8.x4.shared.b16 {%0,%1,%2,%3}, [%4];"  \
                 : "=r"(R0), "=r"(R1), "=r"(R2), "=r"(R3) : "r"(ADDR))

#define LDSM_X4_T(R0, R1, R2, R3, ADDR)                                            \
    asm volatile("ldmatrix.sync.aligned.m8n8.x4.trans.shared.b16 {%0,%1,%2,%3}, [%4];" \
                 : "=r"(R0), "=r"(R1), "=r"(R2), "=r"(R3) : "r"(ADDR))

#define CP_ASYNC16(SADDR, GPTR)                                                    \
    asm volatile("cp.async.cg.shared.global [%0], [%1], 16;\n" :: "r"(SADDR), "l"(GPTR))

// ===================== pre-pass 1: convert K,V -> bf16 hi/lo scratch ============
__global__ void __launch_bounds__(256)
preconvert_kv(const float* __restrict__ K, const float* __restrict__ V)
{
    const int bh  = blockIdx.y;
    const int idx = blockIdx.x * 256 + threadIdx.x;
    const int token = idx >> 4, c4 = idx & 15;
    const size_t tok = (size_t)bh * S_LEN + token;
    const size_t go  = tok * KVSTR + c4 * 2;

    unsigned h0, l0, h1, l1;
    float4 k = __ldg((const float4*)(K + tok * D_DIM) + c4);
    cvt_hilo2(k.x, k.y, h0, l0);
    cvt_hilo2(k.z, k.w, h1, l1);
    *(uint2*)&g_KH[go] = make_uint2(h0, h1);
    *(uint2*)&g_KL[go] = make_uint2(l0, l1);

    float4 v = __ldg((const float4*)(V + tok * D_DIM) + c4);
    cvt_hilo2(v.x, v.y, h0, l0);
    cvt_hilo2(v.z, v.w, h1, l1);
    *(uint2*)&g_VH[go] = make_uint2(h0, h1);
    *(uint2*)&g_VL[go] = make_uint2(l0, l1);
}

// ===================== pre-pass 2: pack mask to 1 bit/elem ======================
__global__ void __launch_bounds__(256)
pack_mask(const unsigned* __restrict__ M)
{
    const int lane = threadIdx.x & 31;
    const int wglob = (blockIdx.x * 256 + threadIdx.x) >> 5;   // global warp id
    const int nwarps = (gridDim.x * 256) >> 5;
    for (int w = wglob; w < S_LEN * (S_LEN / 32); w += nwarps) {
        unsigned bit = (M[(size_t)w * 32 + lane] != 0u) ? 1u : 0u;
        unsigned word = __ballot_sync(0xffffffffu, bit);
        if (lane == 0) g_mpack[w] = word;
    }
}

// ===================== main fused attention kernel ==============================
__global__ void __launch_bounds__(256, 1)
attn_flash_kernel(const float* __restrict__ Q,
                  float* __restrict__ p_val,
                  float* __restrict__ p_attn)
{
    extern __shared__ float smem[];
    const unsigned smem_u32 = (unsigned)__cvta_generic_to_shared(smem);

    const int tid  = threadIdx.x;
    const int warp = tid >> 5;
    const int lane = tid & 31;
    const int g    = lane >> 2;
    const int tg   = lane & 3;
    const int bh   = blockIdx.y;
    const int q0   = blockIdx.x * TQ;
    const int ln0  = warp * 16;

    // ---- ldmatrix per-lane byte addresses (buffer 0) ----
    const int qk_row  = ln0 + ((lane >> 4) << 3) + (lane & 7);
    const unsigned qk_off = (unsigned)(qk_row * KVSTR + (((lane >> 3) & 1) << 2)) * 4u;
    const unsigned kh_base = smem_u32 + (OFF_BUF + 0 * ARR_W) * 4u + qk_off;
    const unsigned kl_base = smem_u32 + (OFF_BUF + 1 * ARR_W) * 4u + qk_off;
    const int pv_row  = ln0 + (((lane >> 3) & 1) << 3) + (lane & 7);
    const unsigned pv_off = (unsigned)(pv_row * KVSTR + ((lane >> 4) << 2)) * 4u;
    const unsigned vh_base = smem_u32 + (OFF_BUF + 2 * ARR_W) * 4u + pv_off;
    const unsigned vl_base = smem_u32 + (OFF_BUF + 3 * ARR_W) * 4u + pv_off;

    // ================= Q tile (32 rows) -> smem -> A fragments =================
    {
#pragma unroll
        for (int i = 0; i < 2; i++) {
            int idx = tid + i * 256;
            int row = idx >> 4, c4 = idx & 15;
            float4 qv = __ldg((const float4*)(Q + ((size_t)bh * S_LEN + q0 + row) * D_DIM) + c4);
            *((float4*)(smem + OFF_Q + row * 68 + c4 * 4)) = qv;
        }
    }
    __syncthreads();

    unsigned qah[2][4][4], qal[2][4][4];
#pragma unroll
    for (int m = 0; m < 2; m++) {
        int r0 = m * 16 + g, r1 = m * 16 + g + 8;
#pragma unroll
        for (int ks = 0; ks < 4; ks++) {
            int c = ks * 16 + tg * 2;
            float2 x0 = *(const float2*)(smem + OFF_Q + r0 * 68 + c);
            float2 x1 = *(const float2*)(smem + OFF_Q + r1 * 68 + c);
            float2 x2 = *(const float2*)(smem + OFF_Q + r0 * 68 + c + 8);
            float2 x3 = *(const float2*)(smem + OFF_Q + r1 * 68 + c + 8);
            cvt_hilo2(x0.x, x0.y, qah[m][ks][0], qal[m][ks][0]);
            cvt_hilo2(x1.x, x1.y, qah[m][ks][1], qal[m][ks][1]);
            cvt_hilo2(x2.x, x2.y, qah[m][ks][2], qal[m][ks][2]);
            cvt_hilo2(x3.x, x3.y, qah[m][ks][3], qal[m][ks][3]);
        }
    }

    float rs[4] = {0.f, 0.f, 0.f, 0.f};
    float O[16][4];
#pragma unroll
    for (int j = 0; j < 16; j++) { O[j][0] = O[j][1] = O[j][2] = O[j][3] = 0.f; }

    // mask word pointers (one broadcast word per row per stage) and p_attn rows
    const unsigned* mp[4];
    float* pa[4];
#pragma unroll
    for (int r = 0; r < 4; r++) {
        int row = (r >> 1) * 16 + g + (r & 1) * 8;    // g, g+8, 16+g, 24+g
        mp[r] = g_mpack + (size_t)(q0 + row) * 64 + (warp >> 1);
        pa[r] = p_attn + ((size_t)bh * S_LEN + q0 + row) * S_LEN;
    }
    const unsigned posbase = (warp & 1) * 16;
    const size_t bh_base = (size_t)bh * S_LEN * KVSTR;

    // ---- prologue: issue stage 0 loads ----
    {
        const size_t sb = bh_base;
        for (int i = tid; i < ARR_W / 4; i += 256) {
            unsigned so = (unsigned)(OFF_BUF * 4 + i * 16);
            CP_ASYNC16(smem_u32 + so,                 (const uint4*)(g_KH + sb) + i);
            CP_ASYNC16(smem_u32 + so + ARR_W * 4,     (const uint4*)(g_KL + sb) + i);
            CP_ASYNC16(smem_u32 + so + 2 * ARR_W * 4, (const uint4*)(g_VH + sb) + i);
            CP_ASYNC16(smem_u32 + so + 3 * ARR_W * 4, (const uint4*)(g_VL + sb) + i);
        }
        asm volatile("cp.async.commit_group;\n");
    }

    // =================== pipelined main loop: 16 stages of 128 tokens ==========
    for (int st = 0; st < 16; st++) {
        const int kb0 = st * 128;
        const unsigned bufoff = (unsigned)(st & 1) * (BUF_W * 4);

        asm volatile("cp.async.wait_group 0;\n" ::: "memory");
        __syncthreads();   // stage-st data visible to all; prev compute done

        // ---- prefetch stage st+1 into the other buffer ----
        if (st < 15) {
            const size_t sb = bh_base + (size_t)(kb0 + 128) * KVSTR;
            const unsigned dst = (unsigned)(OFF_BUF * 4) + (unsigned)((st + 1) & 1) * (BUF_W * 4);
            for (int i = tid; i < ARR_W / 4; i += 256) {
                unsigned so = dst + (unsigned)i * 16u;
                CP_ASYNC16(smem_u32 + so,                 (const uint4*)(g_KH + sb) + i);
                CP_ASYNC16(smem_u32 + so + ARR_W * 4,     (const uint4*)(g_KL + sb) + i);
                CP_ASYNC16(smem_u32 + so + 2 * ARR_W * 4, (const uint4*)(g_VH + sb) + i);
                CP_ASYNC16(smem_u32 + so + 3 * ARR_W * 4, (const uint4*)(g_VL + sb) + i);
            }
            asm volatile("cp.async.commit_group;\n");
        }

        // ---- QK^T: 2 M-tiles x warp's 16 tokens, 3-term hi/lo ----
        float C00[4] = {0,0,0,0}, C01[4] = {0,0,0,0};
        float C10[4] = {0,0,0,0}, C11[4] = {0,0,0,0};
#pragma unroll
        for (int ks = 0; ks < 4; ks++) {
            unsigned b0, b1, b2, b3, l0, l1, l2, l3;
            LDSM_X4(b0, b1, b2, b3, kh_base + bufoff + ks * 32u);
            LDSM_X4(l0, l1, l2, l3, kl_base + bufoff + ks * 32u);
            MMA16816(C00, qah[0][ks][0], qah[0][ks][1], qah[0][ks][2], qah[0][ks][3], b0, b1);
            MMA16816(C01, qah[0][ks][0], qah[0][ks][1], qah[0][ks][2], qah[0][ks][3], b2, b3);
            MMA16816(C10, qah[1][ks][0], qah[1][ks][1], qah[1][ks][2], qah[1][ks][3], b0, b1);
            MMA16816(C11, qah[1][ks][0], qah[1][ks][1], qah[1][ks][2], qah[1][ks][3], b2, b3);
            MMA16816(C00, qal[0][ks][0], qal[0][ks][1], qal[0][ks][2], qal[0][ks][3], b0, b1);
            MMA16816(C01, qal[0][ks][0], qal[0][ks][1], qal[0][ks][2], qal[0][ks][3], b2, b3);
            MMA16816(C10, qal[1][ks][0], qal[1][ks][1], qal[1][ks][2], qal[1][ks][3], b0, b1);
            MMA16816(C11, qal[1][ks][0], qal[1][ks][1], qal[1][ks][2], qal[1][ks][3], b2, b3);
            MMA16816(C00, qah[0][ks][0], qah[0][ks][1], qah[0][ks][2], qah[0][ks][3], l0, l1);
            MMA16816(C01, qah[0][ks][0], qah[0][ks][1], qah[0][ks][2], qah[0][ks][3], l2, l3);
            MMA16816(C10, qah[1][ks][0], qah[1][ks][1], qah[1][ks][2], qah[1][ks][3], l0, l1);
            MMA16816(C11, qah[1][ks][0], qah[1][ks][1], qah[1][ks][2], qah[1][ks][3], l2, l3);
        }

        // ---- epilogue: mask(bit), exp, rowsum; unnormalized exp -> p_attn ----
        unsigned mw0 = __ldg(mp[0] + st * 4);
        unsigned mw1 = __ldg(mp[1] + st * 4);
        unsigned mw2 = __ldg(mp[2] + st * 4);
        unsigned mw3 = __ldg(mp[3] + st * 4);
        float e[2][2][4];
#pragma unroll
        for (int m = 0; m < 2; m++) {
            unsigned ma = m ? mw2 : mw0;   // row m*16+g
            unsigned mb = m ? mw3 : mw1;   // row m*16+g+8
#pragma unroll
            for (int t = 0; t < 2; t++) {
                const float* C = m ? (t ? C11 : C10) : (t ? C01 : C00);
                int nb = kb0 + ln0 + t * 8 + tg * 2;
                unsigned sh = posbase + t * 8 + tg * 2;
                float* E = e[m][t];
                E[0] = ((ma >> sh) & 1u)       ? 0.f : __expf(C[0] * 0.125f);
                E[1] = ((ma >> (sh + 1)) & 1u) ? 0.f : __expf(C[1] * 0.125f);
                E[2] = ((mb >> sh) & 1u)       ? 0.f : __expf(C[2] * 0.125f);
                E[3] = ((mb >> (sh + 1)) & 1u) ? 0.f : __expf(C[3] * 0.125f);
                rs[2 * m]     += E[0] + E[1];
                rs[2 * m + 1] += E[2] + E[3];
                *(float2*)(pa[2 * m]     + nb) = make_float2(E[0], E[1]);
                *(float2*)(pa[2 * m + 1] + nb) = make_float2(E[2], E[3]);
            }
        }

        // ---- E -> A-frag hi/lo in registers (C-frag layout == A-frag layout) ----
        unsigned Ah[2][4], Al[2][4];
#pragma unroll
        for (int m = 0; m < 2; m++) {
            cvt_hilo2(e[m][0][0], e[m][0][1], Ah[m][0], Al[m][0]);
            cvt_hilo2(e[m][0][2], e[m][0][3], Ah[m][1], Al[m][1]);
            cvt_hilo2(e[m][1][0], e[m][1][1], Ah[m][2], Al[m][2]);
            cvt_hilo2(e[m][1][2], e[m][1][3], Ah[m][3], Al[m][3]);
        }

        // ---- PV: warp's 16 tokens x all 64 d (4 LDSM.x4.trans pairs) ----
#pragma unroll
        for (int jp = 0; jp < 4; jp++) {
            unsigned b0, b1, b2, b3, l0, l1, l2, l3;
            LDSM_X4_T(b0, b1, b2, b3, vh_base + bufoff + jp * 32u);
            LDSM_X4_T(l0, l1, l2, l3, vl_base + bufoff + jp * 32u);
#pragma unroll
            for (int m = 0; m < 2; m++) {
                float* Oa = O[m * 8 + 2 * jp];
                float* Ob = O[m * 8 + 2 * jp + 1];
                MMA16816(Oa, Ah[m][0], Ah[m][1], Ah[m][2], Ah[m][3], b0, b1);
                MMA16816(Oa, Al[m][0], Al[m][1], Al[m][2], Al[m][3], b0, b1);
                MMA16816(Oa, Ah[m][0], Ah[m][1], Ah[m][2], Ah[m][3], l0, l1);
                MMA16816(Ob, Ah[m][0], Ah[m][1], Ah[m][2], Ah[m][3], b2, b3);
                MMA16816(Ob, Al[m][0], Al[m][1], Al[m][2], Al[m][3], b2, b3);
                MMA16816(Ob, Ah[m][0], Ah[m][1], Ah[m][2], Ah[m][3], l2, l3);
            }
        }
    }

    // ================= rowsums ================================================
#pragma unroll
    for (int r = 0; r < 4; r++) {
        rs[r] += __shfl_xor_sync(0xffffffff, rs[r], 1);
        rs[r] += __shfl_xor_sync(0xffffffff, rs[r], 2);
    }

    __syncthreads();   // last-stage LDSM reads done before O-red overlays buffers

    if (tg == 0) {
#pragma unroll
        for (int r = 0; r < 4; r++) {
            int row = (r >> 1) * 16 + g + (r & 1) * 8;
            smem[OFF_PART + row * 8 + warp] = rs[r];
        }
    }
    {
        float* base = smem + OFF_RED + warp * (32 * REDSTR);
#pragma unroll
        for (int m = 0; m < 2; m++) {
            int r0 = m * 16 + g, r1 = m * 16 + g + 8;
#pragma unroll
            for (int j = 0; j < 8; j++) {
                const float* Oj = O[m * 8 + j];
                *(float2*)(base + r0 * REDSTR + j * 8 + 2 * tg) = make_float2(Oj[0], Oj[1]);
                *(float2*)(base + r1 * REDSTR + j * 8 + 2 * tg) = make_float2(Oj[2], Oj[3]);
            }
        }
    }
    __syncthreads();

    if (tid < TQ) {
        float s = 0.f;
#pragma unroll
        for (int i = 0; i < 8; i++) s += smem[OFF_PART + tid * 8 + i];
        float iv = 1.0f / s;
        smem[OFF_INV + tid] = iv;
        g_inv[(size_t)bh * S_LEN + q0 + tid] = iv;
    }
    __syncthreads();

    // ================= reduce O partials, write p_val =========================
#pragma unroll
    for (int it = 0; it < 2; it++) {
        int item = tid + it * 256;       // 0..511
        int row = item >> 4;
        int d0  = (item & 15) * 4;
        float4 acc = make_float4(0.f, 0.f, 0.f, 0.f);
#pragma unroll
        for (int w = 0; w < 8; w++) {
            float4 v = *(const float4*)(smem + OFF_RED + w * (32 * REDSTR) + row * REDSTR + d0);
            acc.x += v.x; acc.y += v.y; acc.z += v.z; acc.w += v.w;
        }
        float inv = smem[OFF_INV + row];
        acc.x *= inv; acc.y *= inv; acc.z *= inv; acc.w *= inv;
        *(float4*)(p_val + ((size_t)bh * S_LEN + q0 + row) * D_DIM + d0) = acc;
    }
}

// ===================== normalize pass: p_attn *= inv[row] =======================
__global__ void __launch_bounds__(256)
normalize_pattn(float* __restrict__ p_attn)
{
    float4* p4 = (float4*)p_attn;
    const size_t stride = (size_t)gridDim.x * 256;
    size_t i4 = (size_t)blockIdx.x * 256 + threadIdx.x;
#pragma unroll
    for (int it = 0; it < 8; it++) {
        unsigned row = (unsigned)(i4 >> 9);
        float inv = __ldg(&g_inv[row]);
        float4 v = p4[i4];
        v.x *= inv; v.y *= inv; v.z *= inv; v.w *= inv;
        p4[i4] = v;
        i4 += stride;
    }
}

extern "C" void kernel_launch(void* const* d_in, const int* in_sizes, int n_in,
                              void* d_out, int out_size)
{
    const float*    Q = (const float*)d_in[0];
    const float*    K = (const float*)d_in[1];
    const float*    V = (const float*)d_in[2];
    const unsigned* M = (const unsigned*)d_in[3];

    float* p_val  = (float*)d_out;
    float* p_attn = (float*)d_out + (size_t)2 * 16 * 2048 * 64;

    const size_t smem_bytes = (size_t)SMEM_WORDS * sizeof(float);  // 157312
    cudaFuncSetAttribute(attn_flash_kernel,
                         cudaFuncAttributeMaxDynamicSharedMemorySize,
                         (int)smem_bytes);

    preconvert_kv<<<dim3(128, NBH), 256>>>(K, V);
    pack_mask<<<512, 256>>>(M);
    attn_flash_kernel<<<dim3(S_LEN / TQ, NBH), 256, smem_bytes>>>(Q, p_val, p_attn);
    normalize_pattn<<<16384, 256>>>(p_attn);
}